// round 1
// baseline (speedup 1.0000x reference)
#include <cuda_runtime.h>
#include <math.h>

#define B_DIM   4
#define L_DIM   2048
#define D_MODEL 1024
#define N_HEADS 16
#define D_HEAD  64
#define ML      (B_DIM * L_DIM)          /* 8192 rows */
#define N_PAIR  (B_DIM * N_HEADS)        /* 64 scan lanes */
#define N_CHUNK (L_DIM / 64)             /* 32 chunks */
#define STRIDE  65                       /* smem row stride (bank-conflict pad) */

/* ---------------- scratch (device globals; no runtime alloc) ---------------- */
__device__ float g_kpre[ML * D_MODEL];
__device__ float g_qpre[ML * D_MODEL];
__device__ float g_vpre[ML * D_MODEL];
__device__ float g_kn  [ML * D_MODEL];   /* (B,H,L,Dh) normalized k            */
__device__ float g_qn  [ML * D_MODEL];   /* (B,H,L,Dh) normalized q            */
__device__ float g_vs  [ML * D_MODEL];   /* (B,H,L,Dh) eta*silu(v)             */
__device__ float g_bb  [ML * D_MODEL];   /* (B,H,L,Dh) eta*k_n                 */
__device__ float g_o   [ML * D_MODEL];   /* (B,L,Dm) rms-normalized delta out  */

/* ---------------- generic SGEMM: Y[M,N] = X[M,K] @ W[N,K]^T + bias ---------- */
__global__ __launch_bounds__(256) void gemm_nt(
    const float* __restrict__ X, const float* __restrict__ W,
    const float* __restrict__ bias, float* __restrict__ Y,
    int M, int N, int K)
{
    __shared__ float As[8][128];
    __shared__ float Bs[8][128];
    const int tid = threadIdx.x;
    const int tx = tid & 15;
    const int ty = tid >> 4;
    const int bm = blockIdx.y * 128;
    const int bn = blockIdx.x * 128;
    const int lr = tid >> 1;
    const int lc = (tid & 1) * 4;
    const float* Ag = X + (size_t)(bm + lr) * K + lc;
    const float* Bg = W + (size_t)(bn + lr) * K + lc;

    float acc[8][8];
#pragma unroll
    for (int i = 0; i < 8; i++)
#pragma unroll
        for (int j = 0; j < 8; j++) acc[i][j] = 0.f;

    for (int k0 = 0; k0 < K; k0 += 8) {
        float4 a4 = *(const float4*)(Ag + k0);
        float4 b4 = *(const float4*)(Bg + k0);
        As[lc + 0][lr] = a4.x; As[lc + 1][lr] = a4.y;
        As[lc + 2][lr] = a4.z; As[lc + 3][lr] = a4.w;
        Bs[lc + 0][lr] = b4.x; Bs[lc + 1][lr] = b4.y;
        Bs[lc + 2][lr] = b4.z; Bs[lc + 3][lr] = b4.w;
        __syncthreads();
#pragma unroll
        for (int kk = 0; kk < 8; kk++) {
            float a[8], b[8];
            *(float4*)(a + 0) = *(const float4*)(&As[kk][ty * 8]);
            *(float4*)(a + 4) = *(const float4*)(&As[kk][ty * 8 + 4]);
            *(float4*)(b + 0) = *(const float4*)(&Bs[kk][tx * 8]);
            *(float4*)(b + 4) = *(const float4*)(&Bs[kk][tx * 8 + 4]);
#pragma unroll
            for (int i = 0; i < 8; i++)
#pragma unroll
                for (int j = 0; j < 8; j++)
                    acc[i][j] += a[i] * b[j];
        }
        __syncthreads();
    }
#pragma unroll
    for (int i = 0; i < 8; i++) {
        const int row = bm + ty * 8 + i;
        float* yr = Y + (size_t)row * N + bn + tx * 8;
#pragma unroll
        for (int j = 0; j < 8; j++)
            yr[j] = acc[i][j] + bias[bn + tx * 8 + j];
    }
}

/* -------- fused: short-conv(K=4) + beta(sigmoid small GEMM) + silu + L2 norm -
   one CTA per (b,l) token; writes (B,H,L,Dh)-layout tensors for the scan ----- */
__global__ __launch_bounds__(256) void prep_kernel(
    const float* __restrict__ x,
    const float* __restrict__ Wbeta, const float* __restrict__ bbeta,
    const float* __restrict__ ck, const float* __restrict__ cq,
    const float* __restrict__ cv)
{
    __shared__ float xrow[D_MODEL];
    __shared__ float ks[D_MODEL], qs[D_MODEL], vs[D_MODEL];
    __shared__ float eta_s[N_HEADS], kn_s[N_HEADS], qn_s[N_HEADS];

    const int bl = blockIdx.x;              /* b*L + l */
    const int b = bl >> 11;                 /* L = 2048 */
    const int l = bl & 2047;
    const int tid = threadIdx.x;

    for (int d = tid; d < D_MODEL; d += 256) xrow[d] = x[(size_t)bl * D_MODEL + d];

    for (int d = tid; d < D_MODEL; d += 256) {
        float ak = 0.f, aq = 0.f, av = 0.f;
#pragma unroll
        for (int j = 0; j < 4; j++) {
            int ls = l + j - 3;
            if (ls >= 0) {
                size_t idx = ((size_t)b * L_DIM + ls) * D_MODEL + d;
                float wkj = ck[d * 4 + j], wqj = cq[d * 4 + j], wvj = cv[d * 4 + j];
                ak += g_kpre[idx] * wkj;
                aq += g_qpre[idx] * wqj;
                av += g_vpre[idx] * wvj;
            }
        }
        ks[d] = ak; qs[d] = aq; vs[d] = av;
    }
    __syncthreads();

    const int warp = tid >> 5, lane = tid & 31;
    /* beta = sigmoid(x @ Wbeta^T + bbeta) -- uses raw x */
    for (int h = warp; h < N_HEADS; h += 8) {
        float s = 0.f;
        const float* wb = Wbeta + h * D_MODEL;
        for (int k = lane; k < D_MODEL; k += 32) s += xrow[k] * wb[k];
#pragma unroll
        for (int o = 16; o > 0; o >>= 1) s += __shfl_down_sync(0xffffffffu, s, o);
        if (lane == 0) eta_s[h] = 1.f / (1.f + __expf(-(s + bbeta[h])));
    }
    /* per-head L2 norms of conv'd k,q */
    for (int h = warp; h < N_HEADS; h += 8) {
        float a0 = ks[h * 64 + lane], a1 = ks[h * 64 + 32 + lane];
        float sk = a0 * a0 + a1 * a1;
        float q0 = qs[h * 64 + lane], q1 = qs[h * 64 + 32 + lane];
        float sq = q0 * q0 + q1 * q1;
#pragma unroll
        for (int o = 16; o > 0; o >>= 1) {
            sk += __shfl_down_sync(0xffffffffu, sk, o);
            sq += __shfl_down_sync(0xffffffffu, sq, o);
        }
        if (lane == 0) { kn_s[h] = sqrtf(sk); qn_s[h] = sqrtf(sq); }
    }
    __syncthreads();

    for (int d = tid; d < D_MODEL; d += 256) {
        int h = d >> 6;
        float kn = ks[d] / (kn_s[h] + 1e-6f);
        float qn = qs[d] / (qn_s[h] + 1e-6f);
        float vv = vs[d];
        float sv = vv / (1.f + __expf(-vv));
        float e = eta_s[h];
        size_t base = (((size_t)(b * N_HEADS + h)) * L_DIM + l) * D_HEAD + (d & 63);
        g_kn[base] = kn;
        g_qn[base] = qn;
        g_vs[base] = e * sv;
        g_bb[base] = e * kn;
    }
}

/* ---------------- chunked o2b weighted delta-rule scan ----------------------
   one CTA per (b,h) pair; 32 sequential 64-token chunks; W_t / W_avg in smem.
   Fuses RMS-norm over head dim into the chunk epilogue. ----------------------*/
#define SMEM_FLOATS (7 * 64 * STRIDE + 256 + 64)

__global__ __launch_bounds__(256) void delta_kernel(const float* __restrict__ rms_w)
{
    extern __shared__ float sm[];
    float* Wt  = sm;                       /* 64 x 65 */
    float* Wa  = Wt  + 64 * STRIDE;
    float* Ks  = Wa  + 64 * STRIDE;
    float* Qs  = Ks  + 64 * STRIDE;
    float* Us  = Qs  + 64 * STRIDE;        /* V -> RHS -> U */
    float* Bss = Us  + 64 * STRIDE;        /* b tile, reused for O */
    float* Ts  = Bss + 64 * STRIDE;        /* T, reused for QK */
    float* red = Ts  + 64 * STRIDE;        /* 256 */
    float* rw  = red + 256;                /* 64 */

    const int tid = threadIdx.x;
    const int tx = tid & 15;
    const int ty = tid >> 4;
    const int pair = blockIdx.x;
    const int b = pair >> 4, h = pair & 15;

    for (int i = tid; i < 64 * STRIDE; i += 256) { Wt[i] = 0.f; Wa[i] = 0.f; }
    if (tid < 64) rw[tid] = rms_w[tid];

    const size_t pbase = (size_t)pair * L_DIM * D_HEAD;

    for (int chunk = 0; chunk < N_CHUNK; chunk++) {
        __syncthreads();                   /* prior chunk fully consumed */
        const size_t cb = pbase + (size_t)chunk * 64 * D_HEAD;
        for (int i2 = tid; i2 < 4096; i2 += 256) {
            int s = (i2 >> 6) * STRIDE + (i2 & 63);
            Ks[s]  = g_kn[cb + i2];
            Qs[s]  = g_qn[cb + i2];
            Us[s]  = g_vs[cb + i2];
            Bss[s] = g_bb[cb + i2];
        }
        __syncthreads();

        const float ts    = (float)(chunk * 64);
        const float tri0  = 0.5f * (1.f + ts) * ts;
        const float denw  = 0.5f * (65.f + ts) * (64.f + ts);
        const float Ssum  = 64.f * ts + 2080.f;
        const float coef1 = (ts / (ts + 64.f)) * ((1.f + ts) / (ts + 65.f));
        const float coef2 = (64.f / (ts + 64.f)) * ((2.f * ts + 65.f) / (ts + 65.f));

        /* A: T = strict_tril(B @ K^T) */
        {
            float acc[4][4] = {};
            for (int k = 0; k < 64; k++) {
                float a0[4], b0[4];
#pragma unroll
                for (int i = 0; i < 4; i++) a0[i] = Bss[(4 * ty + i) * STRIDE + k];
#pragma unroll
                for (int j = 0; j < 4; j++) b0[j] = Ks[(4 * tx + j) * STRIDE + k];
#pragma unroll
                for (int i = 0; i < 4; i++)
#pragma unroll
                    for (int j = 0; j < 4; j++) acc[i][j] += a0[i] * b0[j];
            }
#pragma unroll
            for (int i = 0; i < 4; i++)
#pragma unroll
                for (int j = 0; j < 4; j++) {
                    int r = 4 * ty + i, c = 4 * tx + j;
                    Ts[r * STRIDE + c] = (r > c) ? acc[i][j] : 0.f;
                }
        }
        __syncthreads();

        /* B: RHS = V - B @ W_t   (into Us) */
        {
            float acc[4][4] = {};
            for (int k = 0; k < 64; k++) {
                float a0[4], w0[4];
#pragma unroll
                for (int i = 0; i < 4; i++) a0[i] = Bss[(4 * ty + i) * STRIDE + k];
#pragma unroll
                for (int j = 0; j < 4; j++) w0[j] = Wt[k * STRIDE + 4 * tx + j];
#pragma unroll
                for (int i = 0; i < 4; i++)
#pragma unroll
                    for (int j = 0; j < 4; j++) acc[i][j] += a0[i] * w0[j];
            }
#pragma unroll
            for (int i = 0; i < 4; i++)
#pragma unroll
                for (int j = 0; j < 4; j++)
                    Us[(4 * ty + i) * STRIDE + 4 * tx + j] -= acc[i][j];
        }
        __syncthreads();

        /* C: forward substitution  (I+T) U = RHS  (unit lower triangular) */
        {
            const int p4 = tid >> 6, dc = tid & 63;
            for (int i = 1; i < 64; i++) {
                float a2 = 0.f;
                for (int j = p4; j < i; j += 4) a2 += Ts[i * STRIDE + j] * Us[j * STRIDE + dc];
                red[p4 * 64 + dc] = a2;
                __syncthreads();
                if (tid < 64)
                    Us[i * STRIDE + tid] -= red[tid] + red[64 + tid] + red[128 + tid] + red[192 + tid];
                __syncthreads();
            }
        }

        /* per-row chunk constants for this thread's 4 rows */
        float csr[4], rdiv[4], arr[4];
#pragma unroll
        for (int i = 0; i < 4; i++) {
            float rr = (float)(4 * ty + i);
            float cs = (rr + 1.f) * ts + 0.5f * (rr + 1.f) * (rr + 2.f);
            csr[i]  = cs;
            rdiv[i] = 1.f / (tri0 + cs);
            arr[i]  = tri0 * rdiv[i];
        }

        /* D: O = (Q @ W_avg)*a + (Q @ W_t)*(1-a)   (old W's) */
        float o[4][4];
        {
            float acc1[4][4] = {}, acc2[4][4] = {};
            for (int k = 0; k < 64; k++) {
                float q0[4], wa0[4], wt0[4];
#pragma unroll
                for (int i = 0; i < 4; i++) q0[i] = Qs[(4 * ty + i) * STRIDE + k];
#pragma unroll
                for (int j = 0; j < 4; j++) {
                    wa0[j] = Wa[k * STRIDE + 4 * tx + j];
                    wt0[j] = Wt[k * STRIDE + 4 * tx + j];
                }
#pragma unroll
                for (int i = 0; i < 4; i++)
#pragma unroll
                    for (int j = 0; j < 4; j++) {
                        acc1[i][j] += q0[i] * wa0[j];
                        acc2[i][j] += q0[i] * wt0[j];
                    }
            }
#pragma unroll
            for (int i = 0; i < 4; i++)
#pragma unroll
                for (int j = 0; j < 4; j++)
                    o[i][j] = acc1[i][j] * arr[i] + acc2[i][j] * (1.f - arr[i]);
        }

        /* E: QK = Q @ K^T  (into Ts; safe - Ts last read before last sync) */
        {
            float acc[4][4] = {};
            for (int k = 0; k < 64; k++) {
                float q0[4], k0[4];
#pragma unroll
                for (int i = 0; i < 4; i++) q0[i] = Qs[(4 * ty + i) * STRIDE + k];
#pragma unroll
                for (int j = 0; j < 4; j++) k0[j] = Ks[(4 * tx + j) * STRIDE + k];
#pragma unroll
                for (int i = 0; i < 4; i++)
#pragma unroll
                    for (int j = 0; j < 4; j++) acc[i][j] += q0[i] * k0[j];
            }
            __syncthreads();   /* everyone done reading Ts in step C path */
#pragma unroll
            for (int i = 0; i < 4; i++)
#pragma unroll
                for (int j = 0; j < 4; j++)
                    Ts[(4 * ty + i) * STRIDE + 4 * tx + j] = acc[i][j];
        }
        __syncthreads();

        /* F: O += (T_mat o QK) @ U */
        {
            for (int kp = 0; kp < 64; kp++) {
                float kf = (float)kp;
                float csk_m = kf * ts + 0.5f * kf * (kf + 1.f);  /* cs[kp]-idx[kp] */
                float u0[4];
#pragma unroll
                for (int j = 0; j < 4; j++) u0[j] = Us[kp * STRIDE + 4 * tx + j];
#pragma unroll
                for (int i = 0; i < 4; i++) {
                    float num  = csr[i] - csk_m;
                    float sfac = (num >= 0.f) ? num * rdiv[i] : 0.f;
                    float sv   = sfac * Ts[(4 * ty + i) * STRIDE + kp];
#pragma unroll
                    for (int j = 0; j < 4; j++) o[i][j] += sv * u0[j];
                }
            }
        }

        /* G: O -> smem (reuse Bss), fused RMS norm, store to g_o (B,L,Dm) */
#pragma unroll
        for (int i = 0; i < 4; i++)
#pragma unroll
            for (int j = 0; j < 4; j++)
                Bss[(4 * ty + i) * STRIDE + 4 * tx + j] = o[i][j];
        __syncthreads();
        {
            const int r = tid >> 2, seg = tid & 3;
            const float* br = Bss + r * STRIDE + seg * 16;
            float ssum = 0.f;
#pragma unroll
            for (int t = 0; t < 16; t++) ssum += br[t] * br[t];
            ssum += __shfl_down_sync(0xffffffffu, ssum, 2);
            ssum += __shfl_down_sync(0xffffffffu, ssum, 1);
            ssum = __shfl_sync(0xffffffffu, ssum, (tid & 31) & ~3);
            float scale = rsqrtf(ssum * (1.f / 64.f) + 1e-6f);
            int l = chunk * 64 + r;
            float* op = g_o + ((size_t)(b * L_DIM + l)) * D_MODEL + h * D_HEAD + seg * 16;
#pragma unroll
            for (int t = 0; t < 16; t++) op[t] = br[t] * scale * rw[seg * 16 + t];
        }

        /* H: W_avg = c1*W_avg + c2*W_t + K^T @ (U * w);  W_t += K^T @ U */
        {
            float p1[4][4] = {}, p2[4][4] = {};
            for (int r = 0; r < 64; r++) {
                float rr   = (float)r;
                float idxr = ts + rr + 1.f;
                float csrr = (rr + 1.f) * ts + 0.5f * (rr + 1.f) * (rr + 2.f);
                float wr   = (idxr + Ssum - csrr) / denw;
                float kv[4], uv[4], uw[4];
#pragma unroll
                for (int i = 0; i < 4; i++) kv[i] = Ks[r * STRIDE + 4 * ty + i];
#pragma unroll
                for (int j = 0; j < 4; j++) { uv[j] = Us[r * STRIDE + 4 * tx + j]; uw[j] = uv[j] * wr; }
#pragma unroll
                for (int i = 0; i < 4; i++)
#pragma unroll
                    for (int j = 0; j < 4; j++) {
                        p1[i][j] += kv[i] * uv[j];
                        p2[i][j] += kv[i] * uw[j];
                    }
            }
#pragma unroll
            for (int i = 0; i < 4; i++)
#pragma unroll
                for (int j = 0; j < 4; j++) {
                    int idx2 = (4 * ty + i) * STRIDE + 4 * tx + j;
                    float wold = Wt[idx2], waold = Wa[idx2];
                    Wa[idx2] = coef1 * waold + coef2 * wold + p2[i][j];
                    Wt[idx2] = wold + p1[i][j];
                }
        }
        /* loop-top __syncthreads() protects reuse */
    }
}

/* ------------------------------- launcher ----------------------------------*/
extern "C" void kernel_launch(void* const* d_in, const int* in_sizes, int n_in,
                              void* d_out, int out_size)
{
    (void)in_sizes; (void)n_in; (void)out_size;
    const float* x     = (const float*)d_in[0];
    const float* Wk    = (const float*)d_in[1];
    const float* bk    = (const float*)d_in[2];
    const float* Wq    = (const float*)d_in[3];
    const float* bq    = (const float*)d_in[4];
    const float* Wv    = (const float*)d_in[5];
    const float* bv    = (const float*)d_in[6];
    const float* Wbeta = (const float*)d_in[7];
    const float* bbeta = (const float*)d_in[8];
    const float* ck    = (const float*)d_in[9];
    const float* cq    = (const float*)d_in[10];
    const float* cv    = (const float*)d_in[11];
    const float* rms_w = (const float*)d_in[12];
    const float* Wout  = (const float*)d_in[13];
    const float* bout  = (const float*)d_in[14];
    float* out = (float*)d_out;

    float *kpre, *qpre, *vpre, *obuf;
    cudaGetSymbolAddress((void**)&kpre, g_kpre);
    cudaGetSymbolAddress((void**)&qpre, g_qpre);
    cudaGetSymbolAddress((void**)&vpre, g_vpre);
    cudaGetSymbolAddress((void**)&obuf, g_o);

    dim3 gg(D_MODEL / 128, ML / 128);

    gemm_nt<<<gg, 256>>>(x, Wk, bk, kpre, ML, D_MODEL, D_MODEL);
    gemm_nt<<<gg, 256>>>(x, Wq, bq, qpre, ML, D_MODEL, D_MODEL);
    gemm_nt<<<gg, 256>>>(x, Wv, bv, vpre, ML, D_MODEL, D_MODEL);

    prep_kernel<<<ML, 256>>>(x, Wbeta, bbeta, ck, cq, cv);

    size_t smem_bytes = SMEM_FLOATS * sizeof(float);
    cudaFuncSetAttribute(delta_kernel, cudaFuncAttributeMaxDynamicSharedMemorySize,
                         (int)smem_bytes);
    delta_kernel<<<N_PAIR, 256, smem_bytes>>>(rms_w);

    gemm_nt<<<gg, 256>>>(obuf, Wout, bout, out, ML, D_MODEL, D_MODEL);
}

// round 2
// speedup vs baseline: 1.1892x; 1.1892x over previous
#include <cuda_runtime.h>
#include <math.h>
#include <stdint.h>

#define B_DIM   4
#define L_DIM   2048
#define D_MODEL 1024
#define N_HEADS 16
#define D_HEAD  64
#define ML      (B_DIM * L_DIM)          /* 8192 rows */
#define N_PAIR  (B_DIM * N_HEADS)        /* 64 scan lanes */
#define N_CHUNK (L_DIM / 64)             /* 32 chunks */
#define STRIDE  65                       /* smem row stride (bank-conflict pad) */

/* ---------------- scratch (device globals; no runtime alloc) ---------------- */
__device__ float g_kpre[ML * D_MODEL];
__device__ float g_qpre[ML * D_MODEL];
__device__ float g_vpre[ML * D_MODEL];
__device__ float g_kn  [ML * D_MODEL];
__device__ float g_qn  [ML * D_MODEL];
__device__ float g_vs  [ML * D_MODEL];
__device__ float g_bb  [ML * D_MODEL];
__device__ float g_o   [ML * D_MODEL];

/* =================== tensor-core SGEMM (3xTF32 split) =======================
   Y[M,N] = X[M,K] @ W[N,K]^T + bias.   Block 128x128x32, 8 warps, warp 64x32.
   A = Ahi+Alo, B = Bhi+Blo (tf32); acc += AhiBhi + AhiBlo + AloBhi (fp32-grade).
   smem row stride 36 floats -> fragment LDS are conflict-free (bank=4g+tg).  */
#define GT_SMEM_FLOATS (4 * 128 * 36)

#define MMA_TF32(d, a, b)                                                     \
    asm volatile(                                                             \
        "mma.sync.aligned.m16n8k8.row.col.f32.tf32.tf32.f32 "                 \
        "{%0,%1,%2,%3}, {%4,%5,%6,%7}, {%8,%9}, {%0,%1,%2,%3};"               \
        : "+f"(d[0]), "+f"(d[1]), "+f"(d[2]), "+f"(d[3])                      \
        : "r"(a[0]), "r"(a[1]), "r"(a[2]), "r"(a[3]), "r"(b[0]), "r"(b[1]))

__device__ __forceinline__ void split_tf32(float v, float& hi, float& lo) {
    uint32_t hb;
    asm("cvt.rna.tf32.f32 %0, %1;" : "=r"(hb) : "f"(v));
    hi = __uint_as_float(hb);
    float rem = v - hi;
    uint32_t lb;
    asm("cvt.rna.tf32.f32 %0, %1;" : "=r"(lb) : "f"(rem));
    lo = __uint_as_float(lb);
}

__global__ __launch_bounds__(256, 1) void gemm_tc(
    const float* __restrict__ X, const float* __restrict__ W,
    const float* __restrict__ bias, float* __restrict__ Y,
    int M, int N, int K)
{
    extern __shared__ float sm[];
    float* Ah = sm;
    float* Al = Ah + 128 * 36;
    float* Bh = Al + 128 * 36;
    float* Bl = Bh + 128 * 36;

    const int tid = threadIdx.x;
    const int bm = blockIdx.y * 128, bn = blockIdx.x * 128;
    const int lane = tid & 31, w = tid >> 5;
    const int wm = (w >> 2) * 64, wn = (w & 3) * 32;
    const int g = lane >> 2, tg = lane & 3;
    const int lr = tid >> 3;          /* 0..31 */
    const int lc = (tid & 7) * 4;     /* 0..28 */

    float acc[4][4][4];
#pragma unroll
    for (int mt = 0; mt < 4; mt++)
#pragma unroll
        for (int nt = 0; nt < 4; nt++)
#pragma unroll
            for (int e = 0; e < 4; e++) acc[mt][nt][e] = 0.f;

    for (int kb = 0; kb < K; kb += 32) {
#pragma unroll
        for (int rep = 0; rep < 4; rep++) {
            const int r = lr + rep * 32;
            float4 a = *(const float4*)(X + (size_t)(bm + r) * K + kb + lc);
            float4 b = *(const float4*)(W + (size_t)(bn + r) * K + kb + lc);
            float av[4] = {a.x, a.y, a.z, a.w};
            float bv[4] = {b.x, b.y, b.z, b.w};
#pragma unroll
            for (int t = 0; t < 4; t++) {
                float hi, lo;
                split_tf32(av[t], hi, lo);
                Ah[r * 36 + lc + t] = hi; Al[r * 36 + lc + t] = lo;
                split_tf32(bv[t], hi, lo);
                Bh[r * 36 + lc + t] = hi; Bl[r * 36 + lc + t] = lo;
            }
        }
        __syncthreads();

#pragma unroll
        for (int kk = 0; kk < 4; kk++) {
            const int kc = kk * 8 + tg;
            uint32_t ah[4][4], al[4][4], bh[4][2], bl[4][2];
#pragma unroll
            for (int mt = 0; mt < 4; mt++) {
                const int r0 = (wm + mt * 16 + g) * 36 + kc;
                ah[mt][0] = __float_as_uint(Ah[r0]);
                ah[mt][1] = __float_as_uint(Ah[r0 + 8 * 36]);
                ah[mt][2] = __float_as_uint(Ah[r0 + 4]);
                ah[mt][3] = __float_as_uint(Ah[r0 + 8 * 36 + 4]);
                al[mt][0] = __float_as_uint(Al[r0]);
                al[mt][1] = __float_as_uint(Al[r0 + 8 * 36]);
                al[mt][2] = __float_as_uint(Al[r0 + 4]);
                al[mt][3] = __float_as_uint(Al[r0 + 8 * 36 + 4]);
            }
#pragma unroll
            for (int nt = 0; nt < 4; nt++) {
                const int r0 = (wn + nt * 8 + g) * 36 + kc;
                bh[nt][0] = __float_as_uint(Bh[r0]);
                bh[nt][1] = __float_as_uint(Bh[r0 + 4]);
                bl[nt][0] = __float_as_uint(Bl[r0]);
                bl[nt][1] = __float_as_uint(Bl[r0 + 4]);
            }
#pragma unroll
            for (int mt = 0; mt < 4; mt++)
#pragma unroll
                for (int nt = 0; nt < 4; nt++) {
                    MMA_TF32(acc[mt][nt], ah[mt], bh[nt]);
                    MMA_TF32(acc[mt][nt], al[mt], bh[nt]);
                    MMA_TF32(acc[mt][nt], ah[mt], bl[nt]);
                }
        }
        __syncthreads();
    }

#pragma unroll
    for (int mt = 0; mt < 4; mt++) {
        const int row = bm + wm + mt * 16 + g;
#pragma unroll
        for (int nt = 0; nt < 4; nt++) {
            const int col = bn + wn + nt * 8 + tg * 2;
            const float b0 = bias[col], b1 = bias[col + 1];
            float2 v0 = make_float2(acc[mt][nt][0] + b0, acc[mt][nt][1] + b1);
            float2 v1 = make_float2(acc[mt][nt][2] + b0, acc[mt][nt][3] + b1);
            *(float2*)(Y + (size_t)row * N + col) = v0;
            *(float2*)(Y + (size_t)(row + 8) * N + col) = v1;
        }
    }
}

/* -------- fused: short-conv(K=4) + beta + silu + L2 norm -------------------- */
__global__ __launch_bounds__(256) void prep_kernel(
    const float* __restrict__ x,
    const float* __restrict__ Wbeta, const float* __restrict__ bbeta,
    const float* __restrict__ ck, const float* __restrict__ cq,
    const float* __restrict__ cv)
{
    __shared__ float xrow[D_MODEL];
    __shared__ float ks[D_MODEL], qs[D_MODEL], vs[D_MODEL];
    __shared__ float eta_s[N_HEADS], kn_s[N_HEADS], qn_s[N_HEADS];

    const int bl = blockIdx.x;
    const int b = bl >> 11;
    const int l = bl & 2047;
    const int tid = threadIdx.x;

    for (int d = tid; d < D_MODEL; d += 256) xrow[d] = x[(size_t)bl * D_MODEL + d];

    for (int d = tid; d < D_MODEL; d += 256) {
        float ak = 0.f, aq = 0.f, av = 0.f;
#pragma unroll
        for (int j = 0; j < 4; j++) {
            int ls = l + j - 3;
            if (ls >= 0) {
                size_t idx = ((size_t)b * L_DIM + ls) * D_MODEL + d;
                ak += g_kpre[idx] * ck[d * 4 + j];
                aq += g_qpre[idx] * cq[d * 4 + j];
                av += g_vpre[idx] * cv[d * 4 + j];
            }
        }
        ks[d] = ak; qs[d] = aq; vs[d] = av;
    }
    __syncthreads();

    const int warp = tid >> 5, lane = tid & 31;
    for (int h = warp; h < N_HEADS; h += 8) {
        float s = 0.f;
        const float* wb = Wbeta + h * D_MODEL;
        for (int k = lane; k < D_MODEL; k += 32) s += xrow[k] * wb[k];
#pragma unroll
        for (int o = 16; o > 0; o >>= 1) s += __shfl_down_sync(0xffffffffu, s, o);
        if (lane == 0) eta_s[h] = 1.f / (1.f + __expf(-(s + bbeta[h])));
    }
    for (int h = warp; h < N_HEADS; h += 8) {
        float a0 = ks[h * 64 + lane], a1 = ks[h * 64 + 32 + lane];
        float sk = a0 * a0 + a1 * a1;
        float q0 = qs[h * 64 + lane], q1 = qs[h * 64 + 32 + lane];
        float sq = q0 * q0 + q1 * q1;
#pragma unroll
        for (int o = 16; o > 0; o >>= 1) {
            sk += __shfl_down_sync(0xffffffffu, sk, o);
            sq += __shfl_down_sync(0xffffffffu, sq, o);
        }
        if (lane == 0) { kn_s[h] = sqrtf(sk); qn_s[h] = sqrtf(sq); }
    }
    __syncthreads();

    for (int d = tid; d < D_MODEL; d += 256) {
        int h = d >> 6;
        float kn = ks[d] / (kn_s[h] + 1e-6f);
        float qn = qs[d] / (qn_s[h] + 1e-6f);
        float vv = vs[d];
        float sv = vv / (1.f + __expf(-vv));
        float e = eta_s[h];
        size_t base = (((size_t)(b * N_HEADS + h)) * L_DIM + l) * D_HEAD + (d & 63);
        g_kn[base] = kn;
        g_qn[base] = qn;
        g_vs[base] = e * sv;
        g_bb[base] = e * kn;
    }
}

/* ---------------- chunked o2b weighted delta-rule scan ---------------------- */
#define SMEM_FLOATS (7 * 64 * STRIDE + 256 + 64)

__global__ __launch_bounds__(256) void delta_kernel(const float* __restrict__ rms_w)
{
    extern __shared__ float smd[];
    float* Wt  = smd;
    float* Wa  = Wt  + 64 * STRIDE;
    float* Ks  = Wa  + 64 * STRIDE;
    float* Qs  = Ks  + 64 * STRIDE;
    float* Us  = Qs  + 64 * STRIDE;
    float* Bss = Us  + 64 * STRIDE;
    float* Ts  = Bss + 64 * STRIDE;
    float* red = Ts  + 64 * STRIDE;
    float* rw  = red + 256;

    const int tid = threadIdx.x;
    const int tx = tid & 15;
    const int ty = tid >> 4;
    const int pair = blockIdx.x;
    const int b = pair >> 4, h = pair & 15;

    for (int i = tid; i < 64 * STRIDE; i += 256) { Wt[i] = 0.f; Wa[i] = 0.f; }
    if (tid < 64) rw[tid] = rms_w[tid];

    const size_t pbase = (size_t)pair * L_DIM * D_HEAD;

    for (int chunk = 0; chunk < N_CHUNK; chunk++) {
        __syncthreads();
        const size_t cb = pbase + (size_t)chunk * 64 * D_HEAD;
        for (int i2 = tid; i2 < 4096; i2 += 256) {
            int s = (i2 >> 6) * STRIDE + (i2 & 63);
            Ks[s]  = g_kn[cb + i2];
            Qs[s]  = g_qn[cb + i2];
            Us[s]  = g_vs[cb + i2];
            Bss[s] = g_bb[cb + i2];
        }
        __syncthreads();

        const float ts    = (float)(chunk * 64);
        const float tri0  = 0.5f * (1.f + ts) * ts;
        const float denw  = 0.5f * (65.f + ts) * (64.f + ts);
        const float Ssum  = 64.f * ts + 2080.f;
        const float coef1 = (ts / (ts + 64.f)) * ((1.f + ts) / (ts + 65.f));
        const float coef2 = (64.f / (ts + 64.f)) * ((2.f * ts + 65.f) / (ts + 65.f));

        /* A: T = strict_tril(B @ K^T) */
        {
            float acc[4][4] = {};
            for (int k = 0; k < 64; k++) {
                float a0[4], b0[4];
#pragma unroll
                for (int i = 0; i < 4; i++) a0[i] = Bss[(4 * ty + i) * STRIDE + k];
#pragma unroll
                for (int j = 0; j < 4; j++) b0[j] = Ks[(4 * tx + j) * STRIDE + k];
#pragma unroll
                for (int i = 0; i < 4; i++)
#pragma unroll
                    for (int j = 0; j < 4; j++) acc[i][j] += a0[i] * b0[j];
            }
#pragma unroll
            for (int i = 0; i < 4; i++)
#pragma unroll
                for (int j = 0; j < 4; j++) {
                    int r = 4 * ty + i, c = 4 * tx + j;
                    Ts[r * STRIDE + c] = (r > c) ? acc[i][j] : 0.f;
                }
        }
        __syncthreads();

        /* B: RHS = V - B @ W_t */
        {
            float acc[4][4] = {};
            for (int k = 0; k < 64; k++) {
                float a0[4], w0[4];
#pragma unroll
                for (int i = 0; i < 4; i++) a0[i] = Bss[(4 * ty + i) * STRIDE + k];
#pragma unroll
                for (int j = 0; j < 4; j++) w0[j] = Wt[k * STRIDE + 4 * tx + j];
#pragma unroll
                for (int i = 0; i < 4; i++)
#pragma unroll
                    for (int j = 0; j < 4; j++) acc[i][j] += a0[i] * w0[j];
            }
#pragma unroll
            for (int i = 0; i < 4; i++)
#pragma unroll
                for (int j = 0; j < 4; j++)
                    Us[(4 * ty + i) * STRIDE + 4 * tx + j] -= acc[i][j];
        }
        __syncthreads();

        /* C: forward substitution  (I+T) U = RHS */
        {
            const int p4 = tid >> 6, dc = tid & 63;
            for (int i = 1; i < 64; i++) {
                float a2 = 0.f;
                for (int j = p4; j < i; j += 4) a2 += Ts[i * STRIDE + j] * Us[j * STRIDE + dc];
                red[p4 * 64 + dc] = a2;
                __syncthreads();
                if (tid < 64)
                    Us[i * STRIDE + tid] -= red[tid] + red[64 + tid] + red[128 + tid] + red[192 + tid];
                __syncthreads();
            }
        }

        float csr[4], rdiv[4], arr[4];
#pragma unroll
        for (int i = 0; i < 4; i++) {
            float rr = (float)(4 * ty + i);
            float cs = (rr + 1.f) * ts + 0.5f * (rr + 1.f) * (rr + 2.f);
            csr[i]  = cs;
            rdiv[i] = 1.f / (tri0 + cs);
            arr[i]  = tri0 * rdiv[i];
        }

        /* D: O = (Q @ W_avg)*a + (Q @ W_t)*(1-a) */
        float o[4][4];
        {
            float acc1[4][4] = {}, acc2[4][4] = {};
            for (int k = 0; k < 64; k++) {
                float q0[4], wa0[4], wt0[4];
#pragma unroll
                for (int i = 0; i < 4; i++) q0[i] = Qs[(4 * ty + i) * STRIDE + k];
#pragma unroll
                for (int j = 0; j < 4; j++) {
                    wa0[j] = Wa[k * STRIDE + 4 * tx + j];
                    wt0[j] = Wt[k * STRIDE + 4 * tx + j];
                }
#pragma unroll
                for (int i = 0; i < 4; i++)
#pragma unroll
                    for (int j = 0; j < 4; j++) {
                        acc1[i][j] += q0[i] * wa0[j];
                        acc2[i][j] += q0[i] * wt0[j];
                    }
            }
#pragma unroll
            for (int i = 0; i < 4; i++)
#pragma unroll
                for (int j = 0; j < 4; j++)
                    o[i][j] = acc1[i][j] * arr[i] + acc2[i][j] * (1.f - arr[i]);
        }

        /* E: QK = Q @ K^T (into Ts) */
        {
            float acc[4][4] = {};
            for (int k = 0; k < 64; k++) {
                float q0[4], k0[4];
#pragma unroll
                for (int i = 0; i < 4; i++) q0[i] = Qs[(4 * ty + i) * STRIDE + k];
#pragma unroll
                for (int j = 0; j < 4; j++) k0[j] = Ks[(4 * tx + j) * STRIDE + k];
#pragma unroll
                for (int i = 0; i < 4; i++)
#pragma unroll
                    for (int j = 0; j < 4; j++) acc[i][j] += q0[i] * k0[j];
            }
            __syncthreads();
#pragma unroll
            for (int i = 0; i < 4; i++)
#pragma unroll
                for (int j = 0; j < 4; j++)
                    Ts[(4 * ty + i) * STRIDE + 4 * tx + j] = acc[i][j];
        }
        __syncthreads();

        /* F: O += (T_mat o QK) @ U */
        {
            for (int kp = 0; kp < 64; kp++) {
                float kf = (float)kp;
                float csk_m = kf * ts + 0.5f * kf * (kf + 1.f);
                float u0[4];
#pragma unroll
                for (int j = 0; j < 4; j++) u0[j] = Us[kp * STRIDE + 4 * tx + j];
#pragma unroll
                for (int i = 0; i < 4; i++) {
                    float num  = csr[i] - csk_m;
                    float sfac = (num >= 0.f) ? num * rdiv[i] : 0.f;
                    float sv   = sfac * Ts[(4 * ty + i) * STRIDE + kp];
#pragma unroll
                    for (int j = 0; j < 4; j++) o[i][j] += sv * u0[j];
                }
            }
        }

        /* G: O -> smem, fused RMS norm, store */
#pragma unroll
        for (int i = 0; i < 4; i++)
#pragma unroll
            for (int j = 0; j < 4; j++)
                Bss[(4 * ty + i) * STRIDE + 4 * tx + j] = o[i][j];
        __syncthreads();
        {
            const int r = tid >> 2, seg = tid & 3;
            const float* br = Bss + r * STRIDE + seg * 16;
            float ssum = 0.f;
#pragma unroll
            for (int t = 0; t < 16; t++) ssum += br[t] * br[t];
            ssum += __shfl_down_sync(0xffffffffu, ssum, 2);
            ssum += __shfl_down_sync(0xffffffffu, ssum, 1);
            ssum = __shfl_sync(0xffffffffu, ssum, (tid & 31) & ~3);
            float scale = rsqrtf(ssum * (1.f / 64.f) + 1e-6f);
            int l = chunk * 64 + r;
            float* op = g_o + ((size_t)(b * L_DIM + l)) * D_MODEL + h * D_HEAD + seg * 16;
#pragma unroll
            for (int t = 0; t < 16; t++) op[t] = br[t] * scale * rw[seg * 16 + t];
        }

        /* H: W updates */
        {
            float p1[4][4] = {}, p2[4][4] = {};
            for (int r = 0; r < 64; r++) {
                float rr   = (float)r;
                float idxr = ts + rr + 1.f;
                float csrr = (rr + 1.f) * ts + 0.5f * (rr + 1.f) * (rr + 2.f);
                float wr   = (idxr + Ssum - csrr) / denw;
                float kv[4], uv[4], uw[4];
#pragma unroll
                for (int i = 0; i < 4; i++) kv[i] = Ks[r * STRIDE + 4 * ty + i];
#pragma unroll
                for (int j = 0; j < 4; j++) { uv[j] = Us[r * STRIDE + 4 * tx + j]; uw[j] = uv[j] * wr; }
#pragma unroll
                for (int i = 0; i < 4; i++)
#pragma unroll
                    for (int j = 0; j < 4; j++) {
                        p1[i][j] += kv[i] * uv[j];
                        p2[i][j] += kv[i] * uw[j];
                    }
            }
#pragma unroll
            for (int i = 0; i < 4; i++)
#pragma unroll
                for (int j = 0; j < 4; j++) {
                    int idx2 = (4 * ty + i) * STRIDE + 4 * tx + j;
                    float wold = Wt[idx2], waold = Wa[idx2];
                    Wa[idx2] = coef1 * waold + coef2 * wold + p2[i][j];
                    Wt[idx2] = wold + p1[i][j];
                }
        }
    }
}

/* ------------------------------- launcher ----------------------------------*/
extern "C" void kernel_launch(void* const* d_in, const int* in_sizes, int n_in,
                              void* d_out, int out_size)
{
    (void)in_sizes; (void)n_in; (void)out_size;
    const float* x     = (const float*)d_in[0];
    const float* Wk    = (const float*)d_in[1];
    const float* bk    = (const float*)d_in[2];
    const float* Wq    = (const float*)d_in[3];
    const float* bq    = (const float*)d_in[4];
    const float* Wv    = (const float*)d_in[5];
    const float* bv    = (const float*)d_in[6];
    const float* Wbeta = (const float*)d_in[7];
    const float* bbeta = (const float*)d_in[8];
    const float* ck    = (const float*)d_in[9];
    const float* cq    = (const float*)d_in[10];
    const float* cv    = (const float*)d_in[11];
    const float* rms_w = (const float*)d_in[12];
    const float* Wout  = (const float*)d_in[13];
    const float* bout  = (const float*)d_in[14];
    float* out = (float*)d_out;

    float *kpre, *qpre, *vpre, *obuf;
    cudaGetSymbolAddress((void**)&kpre, g_kpre);
    cudaGetSymbolAddress((void**)&qpre, g_qpre);
    cudaGetSymbolAddress((void**)&vpre, g_vpre);
    cudaGetSymbolAddress((void**)&obuf, g_o);

    const size_t gt_smem = GT_SMEM_FLOATS * sizeof(float);
    cudaFuncSetAttribute(gemm_tc, cudaFuncAttributeMaxDynamicSharedMemorySize,
                         (int)gt_smem);

    dim3 gg(D_MODEL / 128, ML / 128);

    gemm_tc<<<gg, 256, gt_smem>>>(x, Wk, bk, kpre, ML, D_MODEL, D_MODEL);
    gemm_tc<<<gg, 256, gt_smem>>>(x, Wq, bq, qpre, ML, D_MODEL, D_MODEL);
    gemm_tc<<<gg, 256, gt_smem>>>(x, Wv, bv, vpre, ML, D_MODEL, D_MODEL);

    prep_kernel<<<ML, 256>>>(x, Wbeta, bbeta, ck, cq, cv);

    size_t smem_bytes = SMEM_FLOATS * sizeof(float);
    cudaFuncSetAttribute(delta_kernel, cudaFuncAttributeMaxDynamicSharedMemorySize,
                         (int)smem_bytes);
    delta_kernel<<<N_PAIR, 256, smem_bytes>>>(rms_w);

    gemm_tc<<<gg, 256, gt_smem>>>(obuf, Wout, bout, out, ML, D_MODEL, D_MODEL);
}

// round 4
// speedup vs baseline: 1.3677x; 1.1501x over previous
#include <cuda_runtime.h>
#include <cuda_fp16.h>
#include <math.h>
#include <stdint.h>

#define B_DIM   4
#define L_DIM   2048
#define D_MODEL 1024
#define N_HEADS 16
#define D_HEAD  64
#define ML      (B_DIM * L_DIM)          /* 8192 rows */
#define N_PAIR  (B_DIM * N_HEADS)        /* 64 scan lanes */
#define N_CHUNK (L_DIM / 64)             /* 32 chunks */
#define STRIDE  65                       /* delta smem row stride */

/* ---------------- scratch (device globals; no runtime alloc) ---------------- */
__device__ float g_kpre[ML * D_MODEL];
__device__ float g_qpre[ML * D_MODEL];
__device__ float g_vpre[ML * D_MODEL];
__device__ float g_kn  [ML * D_MODEL];
__device__ float g_qn  [ML * D_MODEL];
__device__ float g_vs  [ML * D_MODEL];
__device__ float g_bb  [ML * D_MODEL];
__device__ float g_o   [ML * D_MODEL];

/* =================== tensor-core SGEMM (3x FP16 split) ======================
   Y[M,N] = X[M,K] @ W[N,K]^T + bias.  Block 128x128x32, 8 warps, warp 64x32.
   A = Ah+Al, B = Bh+Bl in fp16; acc += AhBh + AhBl + AlBh (fp32 accumulate,
   ~2^-21 element error).  m16n8k16 HMMA = 2x the tf32 legacy rate.
   smem stride 40 halves -> fragment LDS conflict-free (bank = 20g+tg).      */

#define HSTR 40   /* halves per smem row */

#define MMA_F16(d, a, b)                                                      \
    asm volatile(                                                             \
        "mma.sync.aligned.m16n8k16.row.col.f32.f16.f16.f32 "                  \
        "{%0,%1,%2,%3}, {%4,%5,%6,%7}, {%8,%9}, {%0,%1,%2,%3};"               \
        : "+f"(d[0]), "+f"(d[1]), "+f"(d[2]), "+f"(d[3])                      \
        : "r"(a[0]), "r"(a[1]), "r"(a[2]), "r"(a[3]), "r"(b[0]), "r"(b[1]))

__device__ __forceinline__ uint32_t pack_hi(float x, float y, float& rx, float& ry) {
    __half hx = __float2half_rn(x), hy = __float2half_rn(y);
    rx = x - __half2float(hx);
    ry = y - __half2float(hy);
    __half2 p = __halves2half2(hx, hy);
    return *(uint32_t*)&p;
}
__device__ __forceinline__ uint32_t pack_lo(float rx, float ry) {
    __half2 p = __halves2half2(__float2half_rn(rx), __float2half_rn(ry));
    return *(uint32_t*)&p;
}

__global__ __launch_bounds__(256) void gemm_h3(
    const float* __restrict__ X, const float* __restrict__ W,
    const float* __restrict__ bias, float* __restrict__ Y,
    int M, int N, int K)
{
    __shared__ __half Ah[128 * HSTR];
    __shared__ __half Al[128 * HSTR];
    __shared__ __half Bh[128 * HSTR];
    __shared__ __half Bl[128 * HSTR];

    const int tid = threadIdx.x;
    const int bm = blockIdx.y * 128, bn = blockIdx.x * 128;
    const int lane = tid & 31, w = tid >> 5;
    const int wm = (w >> 2) * 64, wn = (w & 3) * 32;
    const int g = lane >> 2, tg = lane & 3;
    const int lr8 = tid >> 3;          /* 0..31 */
    const int lc8 = tid & 7;           /* 0..7  (x4 floats) */

    float acc[4][4][4];
#pragma unroll
    for (int mt = 0; mt < 4; mt++)
#pragma unroll
        for (int nt = 0; nt < 4; nt++)
#pragma unroll
            for (int e = 0; e < 4; e++) acc[mt][nt][e] = 0.f;

    for (int kb = 0; kb < K; kb += 32) {
#pragma unroll
        for (int rep = 0; rep < 4; rep++) {
            const int row = rep * 32 + lr8;
            const int ho = row * HSTR + lc8 * 4;
            float4 a = *(const float4*)(X + (size_t)(bm + row) * K + kb + lc8 * 4);
            float4 b = *(const float4*)(W + (size_t)(bn + row) * K + kb + lc8 * 4);
            float r0, r1, r2, r3;
            uint32_t h01 = pack_hi(a.x, a.y, r0, r1);
            uint32_t h23 = pack_hi(a.z, a.w, r2, r3);
            *(uint32_t*)&Ah[ho]     = h01;
            *(uint32_t*)&Ah[ho + 2] = h23;
            *(uint32_t*)&Al[ho]     = pack_lo(r0, r1);
            *(uint32_t*)&Al[ho + 2] = pack_lo(r2, r3);
            h01 = pack_hi(b.x, b.y, r0, r1);
            h23 = pack_hi(b.z, b.w, r2, r3);
            *(uint32_t*)&Bh[ho]     = h01;
            *(uint32_t*)&Bh[ho + 2] = h23;
            *(uint32_t*)&Bl[ho]     = pack_lo(r0, r1);
            *(uint32_t*)&Bl[ho + 2] = pack_lo(r2, r3);
        }
        __syncthreads();

#pragma unroll
        for (int kk = 0; kk < 2; kk++) {
            const int kc = kk * 16 + 2 * tg;
            uint32_t ah[4][4], al[4][4], bh[4][2], bl[4][2];
#pragma unroll
            for (int mt = 0; mt < 4; mt++) {
                const int r0 = (wm + mt * 16 + g) * HSTR + kc;
                ah[mt][0] = *(const uint32_t*)&Ah[r0];
                ah[mt][1] = *(const uint32_t*)&Ah[r0 + 8 * HSTR];
                ah[mt][2] = *(const uint32_t*)&Ah[r0 + 8];
                ah[mt][3] = *(const uint32_t*)&Ah[r0 + 8 * HSTR + 8];
                al[mt][0] = *(const uint32_t*)&Al[r0];
                al[mt][1] = *(const uint32_t*)&Al[r0 + 8 * HSTR];
                al[mt][2] = *(const uint32_t*)&Al[r0 + 8];
                al[mt][3] = *(const uint32_t*)&Al[r0 + 8 * HSTR + 8];
            }
#pragma unroll
            for (int nt = 0; nt < 4; nt++) {
                const int r0 = (wn + nt * 8 + g) * HSTR + kc;
                bh[nt][0] = *(const uint32_t*)&Bh[r0];
                bh[nt][1] = *(const uint32_t*)&Bh[r0 + 8];
                bl[nt][0] = *(const uint32_t*)&Bl[r0];
                bl[nt][1] = *(const uint32_t*)&Bl[r0 + 8];
            }
#pragma unroll
            for (int mt = 0; mt < 4; mt++)
#pragma unroll
                for (int nt = 0; nt < 4; nt++) {
                    MMA_F16(acc[mt][nt], ah[mt], bh[nt]);
                    MMA_F16(acc[mt][nt], ah[mt], bl[nt]);
                    MMA_F16(acc[mt][nt], al[mt], bh[nt]);
                }
        }
        __syncthreads();
    }

#pragma unroll
    for (int mt = 0; mt < 4; mt++) {
        const int row = bm + wm + mt * 16 + g;
#pragma unroll
        for (int nt = 0; nt < 4; nt++) {
            const int col = bn + wn + nt * 8 + tg * 2;
            const float b0 = bias[col], b1 = bias[col + 1];
            float2 v0 = make_float2(acc[mt][nt][0] + b0, acc[mt][nt][1] + b1);
            float2 v1 = make_float2(acc[mt][nt][2] + b0, acc[mt][nt][3] + b1);
            *(float2*)(Y + (size_t)row * N + col) = v0;
            *(float2*)(Y + (size_t)(row + 8) * N + col) = v1;
        }
    }
}

/* -------- fused: short-conv(K=4) + beta + silu + L2 norm -------------------- */
__global__ __launch_bounds__(256) void prep_kernel(
    const float* __restrict__ x,
    const float* __restrict__ Wbeta, const float* __restrict__ bbeta,
    const float* __restrict__ ck, const float* __restrict__ cq,
    const float* __restrict__ cv)
{
    __shared__ float xrow[D_MODEL];
    __shared__ float ks[D_MODEL], qs[D_MODEL], vs[D_MODEL];
    __shared__ float eta_s[N_HEADS], kn_s[N_HEADS], qn_s[N_HEADS];

    const int bl = blockIdx.x;
    const int b = bl >> 11;
    const int l = bl & 2047;
    const int tid = threadIdx.x;

    for (int d = tid; d < D_MODEL; d += 256) xrow[d] = x[(size_t)bl * D_MODEL + d];

    for (int d = tid; d < D_MODEL; d += 256) {
        float ak = 0.f, aq = 0.f, av = 0.f;
#pragma unroll
        for (int j = 0; j < 4; j++) {
            int ls = l + j - 3;
            if (ls >= 0) {
                size_t idx = ((size_t)b * L_DIM + ls) * D_MODEL + d;
                ak += g_kpre[idx] * ck[d * 4 + j];
                aq += g_qpre[idx] * cq[d * 4 + j];
                av += g_vpre[idx] * cv[d * 4 + j];
            }
        }
        ks[d] = ak; qs[d] = aq; vs[d] = av;
    }
    __syncthreads();

    const int warp = tid >> 5, lane = tid & 31;
    for (int h = warp; h < N_HEADS; h += 8) {
        float s = 0.f;
        const float* wb = Wbeta + h * D_MODEL;
        for (int k = lane; k < D_MODEL; k += 32) s += xrow[k] * wb[k];
#pragma unroll
        for (int o = 16; o > 0; o >>= 1) s += __shfl_down_sync(0xffffffffu, s, o);
        if (lane == 0) eta_s[h] = 1.f / (1.f + __expf(-(s + bbeta[h])));
    }
    for (int h = warp; h < N_HEADS; h += 8) {
        float a0 = ks[h * 64 + lane], a1 = ks[h * 64 + 32 + lane];
        float sk = a0 * a0 + a1 * a1;
        float q0 = qs[h * 64 + lane], q1 = qs[h * 64 + 32 + lane];
        float sq = q0 * q0 + q1 * q1;
#pragma unroll
        for (int o = 16; o > 0; o >>= 1) {
            sk += __shfl_down_sync(0xffffffffu, sk, o);
            sq += __shfl_down_sync(0xffffffffu, sq, o);
        }
        if (lane == 0) { kn_s[h] = sqrtf(sk); qn_s[h] = sqrtf(sq); }
    }
    __syncthreads();

    for (int d = tid; d < D_MODEL; d += 256) {
        int h = d >> 6;
        float kn = ks[d] / (kn_s[h] + 1e-6f);
        float qn = qs[d] / (qn_s[h] + 1e-6f);
        float vv = vs[d];
        float sv = vv / (1.f + __expf(-vv));
        float e = eta_s[h];
        size_t base = (((size_t)(b * N_HEADS + h)) * L_DIM + l) * D_HEAD + (d & 63);
        g_kn[base] = kn;
        g_qn[base] = qn;
        g_vs[base] = e * sv;
        g_bb[base] = e * kn;
    }
}

/* ---------------- chunked o2b weighted delta-rule scan ---------------------- */
#define SMEM_FLOATS (7 * 64 * STRIDE + 256 + 64)

__global__ __launch_bounds__(256) void delta_kernel(const float* __restrict__ rms_w)
{
    extern __shared__ float smd[];
    float* Wt  = smd;
    float* Wa  = Wt  + 64 * STRIDE;
    float* Ks  = Wa  + 64 * STRIDE;
    float* Qs  = Ks  + 64 * STRIDE;
    float* Us  = Qs  + 64 * STRIDE;
    float* Bss = Us  + 64 * STRIDE;
    float* Ts  = Bss + 64 * STRIDE;
    float* red = Ts  + 64 * STRIDE;
    float* rw  = red + 256;

    const int tid = threadIdx.x;
    const int tx = tid & 15;
    const int ty = tid >> 4;
    const int pair = blockIdx.x;
    const int b = pair >> 4, h = pair & 15;

    for (int i = tid; i < 64 * STRIDE; i += 256) { Wt[i] = 0.f; Wa[i] = 0.f; }
    if (tid < 64) rw[tid] = rms_w[tid];

    const size_t pbase = (size_t)pair * L_DIM * D_HEAD;

    for (int chunk = 0; chunk < N_CHUNK; chunk++) {
        __syncthreads();
        const size_t cb = pbase + (size_t)chunk * 64 * D_HEAD;
        for (int i2 = tid; i2 < 4096; i2 += 256) {
            int s = (i2 >> 6) * STRIDE + (i2 & 63);
            Ks[s]  = g_kn[cb + i2];
            Qs[s]  = g_qn[cb + i2];
            Us[s]  = g_vs[cb + i2];
            Bss[s] = g_bb[cb + i2];
        }
        __syncthreads();

        const float ts    = (float)(chunk * 64);
        const float tri0  = 0.5f * (1.f + ts) * ts;
        const float denw  = 0.5f * (65.f + ts) * (64.f + ts);
        const float Ssum  = 64.f * ts + 2080.f;
        const float coef1 = (ts / (ts + 64.f)) * ((1.f + ts) / (ts + 65.f));
        const float coef2 = (64.f / (ts + 64.f)) * ((2.f * ts + 65.f) / (ts + 65.f));

        /* A: T = strict_tril(B @ K^T) */
        {
            float acc[4][4] = {};
            for (int k = 0; k < 64; k++) {
                float a0[4], b0[4];
#pragma unroll
                for (int i = 0; i < 4; i++) a0[i] = Bss[(4 * ty + i) * STRIDE + k];
#pragma unroll
                for (int j = 0; j < 4; j++) b0[j] = Ks[(4 * tx + j) * STRIDE + k];
#pragma unroll
                for (int i = 0; i < 4; i++)
#pragma unroll
                    for (int j = 0; j < 4; j++) acc[i][j] += a0[i] * b0[j];
            }
#pragma unroll
            for (int i = 0; i < 4; i++)
#pragma unroll
                for (int j = 0; j < 4; j++) {
                    int r = 4 * ty + i, c = 4 * tx + j;
                    Ts[r * STRIDE + c] = (r > c) ? acc[i][j] : 0.f;
                }
        }
        __syncthreads();

        /* B: RHS = V - B @ W_t */
        {
            float acc[4][4] = {};
            for (int k = 0; k < 64; k++) {
                float a0[4], w0[4];
#pragma unroll
                for (int i = 0; i < 4; i++) a0[i] = Bss[(4 * ty + i) * STRIDE + k];
#pragma unroll
                for (int j = 0; j < 4; j++) w0[j] = Wt[k * STRIDE + 4 * tx + j];
#pragma unroll
                for (int i = 0; i < 4; i++)
#pragma unroll
                    for (int j = 0; j < 4; j++) acc[i][j] += a0[i] * w0[j];
            }
#pragma unroll
            for (int i = 0; i < 4; i++)
#pragma unroll
                for (int j = 0; j < 4; j++)
                    Us[(4 * ty + i) * STRIDE + 4 * tx + j] -= acc[i][j];
        }
        __syncthreads();

        /* C: forward substitution  (I+T) U = RHS */
        {
            const int p4 = tid >> 6, dc = tid & 63;
            for (int i = 1; i < 64; i++) {
                float a2 = 0.f;
                for (int j = p4; j < i; j += 4) a2 += Ts[i * STRIDE + j] * Us[j * STRIDE + dc];
                red[p4 * 64 + dc] = a2;
                __syncthreads();
                if (tid < 64)
                    Us[i * STRIDE + tid] -= red[tid] + red[64 + tid] + red[128 + tid] + red[192 + tid];
                __syncthreads();
            }
        }

        float csr[4], rdiv[4], arr[4];
#pragma unroll
        for (int i = 0; i < 4; i++) {
            float rr = (float)(4 * ty + i);
            float cs = (rr + 1.f) * ts + 0.5f * (rr + 1.f) * (rr + 2.f);
            csr[i]  = cs;
            rdiv[i] = 1.f / (tri0 + cs);
            arr[i]  = tri0 * rdiv[i];
        }

        /* D: O = (Q @ W_avg)*a + (Q @ W_t)*(1-a) */
        float o[4][4];
        {
            float acc1[4][4] = {}, acc2[4][4] = {};
            for (int k = 0; k < 64; k++) {
                float q0[4], wa0[4], wt0[4];
#pragma unroll
                for (int i = 0; i < 4; i++) q0[i] = Qs[(4 * ty + i) * STRIDE + k];
#pragma unroll
                for (int j = 0; j < 4; j++) {
                    wa0[j] = Wa[k * STRIDE + 4 * tx + j];
                    wt0[j] = Wt[k * STRIDE + 4 * tx + j];
                }
#pragma unroll
                for (int i = 0; i < 4; i++)
#pragma unroll
                    for (int j = 0; j < 4; j++) {
                        acc1[i][j] += q0[i] * wa0[j];
                        acc2[i][j] += q0[i] * wt0[j];
                    }
            }
#pragma unroll
            for (int i = 0; i < 4; i++)
#pragma unroll
                for (int j = 0; j < 4; j++)
                    o[i][j] = acc1[i][j] * arr[i] + acc2[i][j] * (1.f - arr[i]);
        }

        /* E: QK = Q @ K^T (into Ts) */
        {
            float acc[4][4] = {};
            for (int k = 0; k < 64; k++) {
                float q0[4], k0[4];
#pragma unroll
                for (int i = 0; i < 4; i++) q0[i] = Qs[(4 * ty + i) * STRIDE + k];
#pragma unroll
                for (int j = 0; j < 4; j++) k0[j] = Ks[(4 * tx + j) * STRIDE + k];
#pragma unroll
                for (int i = 0; i < 4; i++)
#pragma unroll
                    for (int j = 0; j < 4; j++) acc[i][j] += q0[i] * k0[j];
            }
            __syncthreads();
#pragma unroll
            for (int i = 0; i < 4; i++)
#pragma unroll
                for (int j = 0; j < 4; j++)
                    Ts[(4 * ty + i) * STRIDE + 4 * tx + j] = acc[i][j];
        }
        __syncthreads();

        /* F: O += (T_mat o QK) @ U */
        {
            for (int kp = 0; kp < 64; kp++) {
                float kf = (float)kp;
                float csk_m = kf * ts + 0.5f * kf * (kf + 1.f);
                float u0[4];
#pragma unroll
                for (int j = 0; j < 4; j++) u0[j] = Us[kp * STRIDE + 4 * tx + j];
#pragma unroll
                for (int i = 0; i < 4; i++) {
                    float num  = csr[i] - csk_m;
                    float sfac = (num >= 0.f) ? num * rdiv[i] : 0.f;
                    float sv   = sfac * Ts[(4 * ty + i) * STRIDE + kp];
#pragma unroll
                    for (int j = 0; j < 4; j++) o[i][j] += sv * u0[j];
                }
            }
        }

        /* G: O -> smem, fused RMS norm, store */
#pragma unroll
        for (int i = 0; i < 4; i++)
#pragma unroll
            for (int j = 0; j < 4; j++)
                Bss[(4 * ty + i) * STRIDE + 4 * tx + j] = o[i][j];
        __syncthreads();
        {
            const int r = tid >> 2, seg = tid & 3;
            const float* br = Bss + r * STRIDE + seg * 16;
            float ssum = 0.f;
#pragma unroll
            for (int t = 0; t < 16; t++) ssum += br[t] * br[t];
            ssum += __shfl_down_sync(0xffffffffu, ssum, 2);
            ssum += __shfl_down_sync(0xffffffffu, ssum, 1);
            ssum = __shfl_sync(0xffffffffu, ssum, (tid & 31) & ~3);
            float scale = rsqrtf(ssum * (1.f / 64.f) + 1e-6f);
            int l = chunk * 64 + r;
            float* op = g_o + ((size_t)(b * L_DIM + l)) * D_MODEL + h * D_HEAD + seg * 16;
#pragma unroll
            for (int t = 0; t < 16; t++) op[t] = br[t] * scale * rw[seg * 16 + t];
        }

        /* H: W updates */
        {
            float p1[4][4] = {}, p2[4][4] = {};
            for (int r = 0; r < 64; r++) {
                float rr   = (float)r;
                float idxr = ts + rr + 1.f;
                float csrr = (rr + 1.f) * ts + 0.5f * (rr + 1.f) * (rr + 2.f);
                float wr   = (idxr + Ssum - csrr) / denw;
                float kv[4], uv[4], uw[4];
#pragma unroll
                for (int i = 0; i < 4; i++) kv[i] = Ks[r * STRIDE + 4 * ty + i];
#pragma unroll
                for (int j = 0; j < 4; j++) { uv[j] = Us[r * STRIDE + 4 * tx + j]; uw[j] = uv[j] * wr; }
#pragma unroll
                for (int i = 0; i < 4; i++)
#pragma unroll
                    for (int j = 0; j < 4; j++) {
                        p1[i][j] += kv[i] * uv[j];
                        p2[i][j] += kv[i] * uw[j];
                    }
            }
#pragma unroll
            for (int i = 0; i < 4; i++)
#pragma unroll
                for (int j = 0; j < 4; j++) {
                    int idx2 = (4 * ty + i) * STRIDE + 4 * tx + j;
                    float wold = Wt[idx2], waold = Wa[idx2];
                    Wa[idx2] = coef1 * waold + coef2 * wold + p2[i][j];
                    Wt[idx2] = wold + p1[i][j];
                }
        }
    }
}

/* ------------------------------- launcher ----------------------------------*/
extern "C" void kernel_launch(void* const* d_in, const int* in_sizes, int n_in,
                              void* d_out, int out_size)
{
    (void)in_sizes; (void)n_in; (void)out_size;
    const float* x     = (const float*)d_in[0];
    const float* Wk    = (const float*)d_in[1];
    const float* bk    = (const float*)d_in[2];
    const float* Wq    = (const float*)d_in[3];
    const float* bq    = (const float*)d_in[4];
    const float* Wv    = (const float*)d_in[5];
    const float* bv    = (const float*)d_in[6];
    const float* Wbeta = (const float*)d_in[7];
    const float* bbeta = (const float*)d_in[8];
    const float* ck    = (const float*)d_in[9];
    const float* cq    = (const float*)d_in[10];
    const float* cv    = (const float*)d_in[11];
    const float* rms_w = (const float*)d_in[12];
    const float* Wout  = (const float*)d_in[13];
    const float* bout  = (const float*)d_in[14];
    float* out = (float*)d_out;

    float *kpre, *qpre, *vpre, *obuf;
    cudaGetSymbolAddress((void**)&kpre, g_kpre);
    cudaGetSymbolAddress((void**)&qpre, g_qpre);
    cudaGetSymbolAddress((void**)&vpre, g_vpre);
    cudaGetSymbolAddress((void**)&obuf, g_o);

    dim3 gg(D_MODEL / 128, ML / 128);

    gemm_h3<<<gg, 256>>>(x, Wk, bk, kpre, ML, D_MODEL, D_MODEL);
    gemm_h3<<<gg, 256>>>(x, Wq, bq, qpre, ML, D_MODEL, D_MODEL);
    gemm_h3<<<gg, 256>>>(x, Wv, bv, vpre, ML, D_MODEL, D_MODEL);

    prep_kernel<<<ML, 256>>>(x, Wbeta, bbeta, ck, cq, cv);

    size_t smem_bytes = SMEM_FLOATS * sizeof(float);
    cudaFuncSetAttribute(delta_kernel, cudaFuncAttributeMaxDynamicSharedMemorySize,
                         (int)smem_bytes);
    delta_kernel<<<N_PAIR, 256, smem_bytes>>>(rms_w);

    gemm_h3<<<gg, 256>>>(obuf, Wout, bout, out, ML, D_MODEL, D_MODEL);
}

// round 5
// speedup vs baseline: 1.4069x; 1.0287x over previous
#include <cuda_runtime.h>
#include <cuda_fp16.h>
#include <math.h>
#include <stdint.h>

#define B_DIM   4
#define L_DIM   2048
#define D_MODEL 1024
#define N_HEADS 16
#define D_HEAD  64
#define ML      (B_DIM * L_DIM)          /* 8192 rows */
#define N_PAIR  (B_DIM * N_HEADS)        /* 64 scan lanes */
#define N_CHUNK (L_DIM / 64)             /* 32 chunks */
#define STRIDE  65                       /* delta smem row stride */
#define DD      (D_MODEL * D_MODEL)

/* ---------------- scratch (device globals; no runtime alloc) ---------------- */
__device__ float  g_kpre[ML * D_MODEL];
__device__ float  g_qpre[ML * D_MODEL];
__device__ float  g_vpre[ML * D_MODEL];
__device__ float  g_kn  [ML * D_MODEL];
__device__ float  g_qn  [ML * D_MODEL];
__device__ float  g_vs  [ML * D_MODEL];
__device__ float  g_bb  [ML * D_MODEL];
__device__ __half g_xh  [ML * D_MODEL];
__device__ __half g_xl  [ML * D_MODEL];
__device__ __half g_oh  [ML * D_MODEL];
__device__ __half g_ol  [ML * D_MODEL];
__device__ __half g_wsh [4 * DD];        /* Wk, Wq, Wv, Wout hi */
__device__ __half g_wsl [4 * DD];        /* Wk, Wq, Wv, Wout lo */

/* ---------------- fp32 -> (hi,lo) fp16 split, vectorized -------------------- */
__global__ __launch_bounds__(256) void split_f2h(
    const float4* __restrict__ src, uint2* __restrict__ hi,
    uint2* __restrict__ lo, int n4)
{
    int i = blockIdx.x * blockDim.x + threadIdx.x;
    if (i >= n4) return;
    float4 v = src[i];
    __half2 h01 = __floats2half2_rn(v.x, v.y);
    __half2 h23 = __floats2half2_rn(v.z, v.w);
    __half2 l01 = __floats2half2_rn(v.x - __low2float(h01), v.y - __high2float(h01));
    __half2 l23 = __floats2half2_rn(v.z - __low2float(h23), v.w - __high2float(h23));
    hi[i] = make_uint2(*(uint32_t*)&h01, *(uint32_t*)&h23);
    lo[i] = make_uint2(*(uint32_t*)&l01, *(uint32_t*)&l23);
}

/* =================== tensor-core GEMM (pre-split 3x FP16) ===================
   Y[M,N] = (Ah+Al)[M,K] @ (Bh+Bl)[N,K]^T + bias, fp32 accumulate.
   Block 128x128x32, 8 warps (warp 64x32), cp.async double buffer, ldmatrix.
   smem rows stride 40 halves (80B): LDSM + cp.async conflict-free.          */

#define HS        40                      /* halves per smem row */
#define ARR_B     10240                   /* 128*40*2 bytes per tile array */
#define BUF_B     (4 * ARR_B)             /* Ah, Al, Bh, Bl */
#define GSM_BYTES (2 * BUF_B)             /* 81920 */

__device__ __forceinline__ uint32_t smem_u32(const void* p) {
    uint32_t a;
    asm("{ .reg .u64 t; cvta.to.shared.u64 t, %1; cvt.u32.u64 %0, t; }"
        : "=r"(a) : "l"(p));
    return a;
}

#define LDSM_X4(r, a)                                                         \
    asm volatile("ldmatrix.sync.aligned.m8n8.x4.shared.b16 "                  \
                 "{%0,%1,%2,%3}, [%4];"                                       \
                 : "=r"((r)[0]), "=r"((r)[1]), "=r"((r)[2]), "=r"((r)[3])     \
                 : "r"(a))

#define MMA_F16B(d, a, b0, b1)                                                \
    asm volatile(                                                             \
        "mma.sync.aligned.m16n8k16.row.col.f32.f16.f16.f32 "                  \
        "{%0,%1,%2,%3}, {%4,%5,%6,%7}, {%8,%9}, {%0,%1,%2,%3};"               \
        : "+f"(d[0]), "+f"(d[1]), "+f"(d[2]), "+f"(d[3])                      \
        : "r"(a[0]), "r"(a[1]), "r"(a[2]), "r"(a[3]), "r"(b0), "r"(b1))

#define CP_ASYNC16(sa, gp)                                                    \
    asm volatile("cp.async.cg.shared.global [%0], [%1], 16;"                  \
                 :: "r"(sa), "l"(gp))

__global__ __launch_bounds__(256) void gemm_h3ld(
    const __half* __restrict__ Ahg, const __half* __restrict__ Alg,
    const __half* __restrict__ Bhg, const __half* __restrict__ Blg,
    const float* __restrict__ bias, float* __restrict__ Y,
    int M, int N, int K)
{
    extern __shared__ char smg[];
    const uint32_t sbase = smem_u32(smg);

    const int tid = threadIdx.x;
    const int bm = blockIdx.y * 128, bn = blockIdx.x * 128;
    const int lane = tid & 31, w = tid >> 5;
    const int wm = (w >> 2) * 64, wn = (w & 3) * 32;
    const int g = lane >> 2, tg = lane & 3;

    /* ldmatrix per-lane address components */
    const int arow = (lane & 7) + ((lane >> 3) & 1) * 8;
    const int acol = (lane >> 4) * 8;
    const int brow = ((lane >> 4) & 1) * 8 + (lane & 7);
    const int bcol = ((lane >> 3) & 1) * 8;

    float acc[4][4][4];
#pragma unroll
    for (int mt = 0; mt < 4; mt++)
#pragma unroll
        for (int nt = 0; nt < 4; nt++)
#pragma unroll
            for (int e = 0; e < 4; e++) acc[mt][nt][e] = 0.f;

    const int n_tiles = K >> 5;

    /* cp.async tile loader: 4 arrays x 2 chunks of 16B per thread */
#define LOAD_TILE(t) do {                                                     \
        const int _buf = (t) & 1;                                             \
        const int _kb = (t) << 5;                                             \
        const uint32_t _sb = sbase + _buf * BUF_B;                            \
        _Pragma("unroll")                                                     \
        for (int _j = 0; _j < 2; _j++) {                                      \
            const int _q = tid * 2 + _j;                                      \
            const int _row = _q >> 2, _c = _q & 3;                            \
            const uint32_t _soff = _row * 80 + _c * 16;                       \
            const size_t _ga = (size_t)(bm + _row) * K + _kb + _c * 8;        \
            const size_t _gb = (size_t)(bn + _row) * K + _kb + _c * 8;        \
            CP_ASYNC16(_sb + _soff,              Ahg + _ga);                  \
            CP_ASYNC16(_sb + ARR_B + _soff,      Alg + _ga);                  \
            CP_ASYNC16(_sb + 2 * ARR_B + _soff,  Bhg + _gb);                  \
            CP_ASYNC16(_sb + 3 * ARR_B + _soff,  Blg + _gb);                  \
        }                                                                     \
        asm volatile("cp.async.commit_group;");                               \
    } while (0)

    LOAD_TILE(0);

    for (int t = 0; t < n_tiles; t++) {
        if (t + 1 < n_tiles) {
            LOAD_TILE(t + 1);
            asm volatile("cp.async.wait_group 1;");
        } else {
            asm volatile("cp.async.wait_group 0;");
        }
        __syncthreads();

        const uint32_t sb = sbase + (t & 1) * BUF_B;
#pragma unroll
        for (int kk = 0; kk < 2; kk++) {
            const int kc = kk * 16;
            uint32_t ah[4][4], al[4][4], bh[2][4], bl[2][4];
#pragma unroll
            for (int mt = 0; mt < 4; mt++) {
                uint32_t ad = sb + ((wm + mt * 16 + arow) * HS + kc + acol) * 2;
                LDSM_X4(ah[mt], ad);
                LDSM_X4(al[mt], ad + ARR_B);
            }
#pragma unroll
            for (int a2 = 0; a2 < 2; a2++) {
                uint32_t ad = sb + 2 * ARR_B +
                              ((wn + a2 * 16 + brow) * HS + kc + bcol) * 2;
                LDSM_X4(bh[a2], ad);
                LDSM_X4(bl[a2], ad + ARR_B);
            }
#pragma unroll
            for (int mt = 0; mt < 4; mt++)
#pragma unroll
                for (int nt = 0; nt < 4; nt++) {
                    const int hi2 = nt >> 1, p = (nt & 1) * 2;
                    MMA_F16B(acc[mt][nt], ah[mt], bh[hi2][p], bh[hi2][p + 1]);
                    MMA_F16B(acc[mt][nt], ah[mt], bl[hi2][p], bl[hi2][p + 1]);
                    MMA_F16B(acc[mt][nt], al[mt], bh[hi2][p], bh[hi2][p + 1]);
                }
        }
        __syncthreads();
    }
#undef LOAD_TILE

#pragma unroll
    for (int mt = 0; mt < 4; mt++) {
        const int row = bm + wm + mt * 16 + g;
#pragma unroll
        for (int nt = 0; nt < 4; nt++) {
            const int col = bn + wn + nt * 8 + tg * 2;
            const float b0 = bias[col], b1 = bias[col + 1];
            float2 v0 = make_float2(acc[mt][nt][0] + b0, acc[mt][nt][1] + b1);
            float2 v1 = make_float2(acc[mt][nt][2] + b0, acc[mt][nt][3] + b1);
            *(float2*)(Y + (size_t)row * N + col) = v0;
            *(float2*)(Y + (size_t)(row + 8) * N + col) = v1;
        }
    }
}

/* -------- fused: short-conv(K=4) + beta + silu + L2 norm -------------------- */
__global__ __launch_bounds__(256) void prep_kernel(
    const float* __restrict__ x,
    const float* __restrict__ Wbeta, const float* __restrict__ bbeta,
    const float* __restrict__ ck, const float* __restrict__ cq,
    const float* __restrict__ cv)
{
    __shared__ float xrow[D_MODEL];
    __shared__ float ks[D_MODEL], qs[D_MODEL], vs[D_MODEL];
    __shared__ float eta_s[N_HEADS], kn_s[N_HEADS], qn_s[N_HEADS];

    const int bl = blockIdx.x;
    const int b = bl >> 11;
    const int l = bl & 2047;
    const int tid = threadIdx.x;

    for (int d = tid; d < D_MODEL; d += 256) xrow[d] = x[(size_t)bl * D_MODEL + d];

    for (int d = tid; d < D_MODEL; d += 256) {
        float ak = 0.f, aq = 0.f, av = 0.f;
#pragma unroll
        for (int j = 0; j < 4; j++) {
            int ls = l + j - 3;
            if (ls >= 0) {
                size_t idx = ((size_t)b * L_DIM + ls) * D_MODEL + d;
                ak += g_kpre[idx] * ck[d * 4 + j];
                aq += g_qpre[idx] * cq[d * 4 + j];
                av += g_vpre[idx] * cv[d * 4 + j];
            }
        }
        ks[d] = ak; qs[d] = aq; vs[d] = av;
    }
    __syncthreads();

    const int warp = tid >> 5, lane = tid & 31;
    for (int h = warp; h < N_HEADS; h += 8) {
        float s = 0.f;
        const float* wb = Wbeta + h * D_MODEL;
        for (int k = lane; k < D_MODEL; k += 32) s += xrow[k] * wb[k];
#pragma unroll
        for (int o = 16; o > 0; o >>= 1) s += __shfl_down_sync(0xffffffffu, s, o);
        if (lane == 0) eta_s[h] = 1.f / (1.f + __expf(-(s + bbeta[h])));
    }
    for (int h = warp; h < N_HEADS; h += 8) {
        float a0 = ks[h * 64 + lane], a1 = ks[h * 64 + 32 + lane];
        float sk = a0 * a0 + a1 * a1;
        float q0 = qs[h * 64 + lane], q1 = qs[h * 64 + 32 + lane];
        float sq = q0 * q0 + q1 * q1;
#pragma unroll
        for (int o = 16; o > 0; o >>= 1) {
            sk += __shfl_down_sync(0xffffffffu, sk, o);
            sq += __shfl_down_sync(0xffffffffu, sq, o);
        }
        if (lane == 0) { kn_s[h] = sqrtf(sk); qn_s[h] = sqrtf(sq); }
    }
    __syncthreads();

    for (int d = tid; d < D_MODEL; d += 256) {
        int h = d >> 6;
        float kn = ks[d] / (kn_s[h] + 1e-6f);
        float qn = qs[d] / (qn_s[h] + 1e-6f);
        float vv = vs[d];
        float sv = vv / (1.f + __expf(-vv));
        float e = eta_s[h];
        size_t base = (((size_t)(b * N_HEADS + h)) * L_DIM + l) * D_HEAD + (d & 63);
        g_kn[base] = kn;
        g_qn[base] = qn;
        g_vs[base] = e * sv;
        g_bb[base] = e * kn;
    }
}

/* ---------------- chunked o2b weighted delta-rule scan ---------------------- */
#define SMEM_FLOATS (7 * 64 * STRIDE + 256 + 64)

__global__ __launch_bounds__(256) void delta_kernel(const float* __restrict__ rms_w)
{
    extern __shared__ float smd[];
    float* Wt  = smd;
    float* Wa  = Wt  + 64 * STRIDE;
    float* Ks  = Wa  + 64 * STRIDE;
    float* Qs  = Ks  + 64 * STRIDE;
    float* Us  = Qs  + 64 * STRIDE;
    float* Bss = Us  + 64 * STRIDE;
    float* Ts  = Bss + 64 * STRIDE;
    float* red = Ts  + 64 * STRIDE;
    float* rw  = red + 256;

    const int tid = threadIdx.x;
    const int tx = tid & 15;
    const int ty = tid >> 4;
    const int pair = blockIdx.x;
    const int b = pair >> 4, h = pair & 15;

    for (int i = tid; i < 64 * STRIDE; i += 256) { Wt[i] = 0.f; Wa[i] = 0.f; }
    if (tid < 64) rw[tid] = rms_w[tid];

    const size_t pbase = (size_t)pair * L_DIM * D_HEAD;

    for (int chunk = 0; chunk < N_CHUNK; chunk++) {
        __syncthreads();
        const size_t cb = pbase + (size_t)chunk * 64 * D_HEAD;
        for (int i2 = tid; i2 < 4096; i2 += 256) {
            int s = (i2 >> 6) * STRIDE + (i2 & 63);
            Ks[s]  = g_kn[cb + i2];
            Qs[s]  = g_qn[cb + i2];
            Us[s]  = g_vs[cb + i2];
            Bss[s] = g_bb[cb + i2];
        }
        __syncthreads();

        const float ts    = (float)(chunk * 64);
        const float tri0  = 0.5f * (1.f + ts) * ts;
        const float denw  = 0.5f * (65.f + ts) * (64.f + ts);
        const float Ssum  = 64.f * ts + 2080.f;
        const float coef1 = (ts / (ts + 64.f)) * ((1.f + ts) / (ts + 65.f));
        const float coef2 = (64.f / (ts + 64.f)) * ((2.f * ts + 65.f) / (ts + 65.f));

        /* A: T = strict_tril(B @ K^T) */
        {
            float acc[4][4] = {};
            for (int k = 0; k < 64; k++) {
                float a0[4], b0[4];
#pragma unroll
                for (int i = 0; i < 4; i++) a0[i] = Bss[(4 * ty + i) * STRIDE + k];
#pragma unroll
                for (int j = 0; j < 4; j++) b0[j] = Ks[(4 * tx + j) * STRIDE + k];
#pragma unroll
                for (int i = 0; i < 4; i++)
#pragma unroll
                    for (int j = 0; j < 4; j++) acc[i][j] += a0[i] * b0[j];
            }
#pragma unroll
            for (int i = 0; i < 4; i++)
#pragma unroll
                for (int j = 0; j < 4; j++) {
                    int r = 4 * ty + i, c = 4 * tx + j;
                    Ts[r * STRIDE + c] = (r > c) ? acc[i][j] : 0.f;
                }
        }
        __syncthreads();

        /* B: RHS = V - B @ W_t */
        {
            float acc[4][4] = {};
            for (int k = 0; k < 64; k++) {
                float a0[4], w0[4];
#pragma unroll
                for (int i = 0; i < 4; i++) a0[i] = Bss[(4 * ty + i) * STRIDE + k];
#pragma unroll
                for (int j = 0; j < 4; j++) w0[j] = Wt[k * STRIDE + 4 * tx + j];
#pragma unroll
                for (int i = 0; i < 4; i++)
#pragma unroll
                    for (int j = 0; j < 4; j++) acc[i][j] += a0[i] * w0[j];
            }
#pragma unroll
            for (int i = 0; i < 4; i++)
#pragma unroll
                for (int j = 0; j < 4; j++)
                    Us[(4 * ty + i) * STRIDE + 4 * tx + j] -= acc[i][j];
        }
        __syncthreads();

        /* C: forward substitution  (I+T) U = RHS */
        {
            const int p4 = tid >> 6, dc = tid & 63;
            for (int i = 1; i < 64; i++) {
                float a2 = 0.f;
                for (int j = p4; j < i; j += 4) a2 += Ts[i * STRIDE + j] * Us[j * STRIDE + dc];
                red[p4 * 64 + dc] = a2;
                __syncthreads();
                if (tid < 64)
                    Us[i * STRIDE + tid] -= red[tid] + red[64 + tid] + red[128 + tid] + red[192 + tid];
                __syncthreads();
            }
        }

        float csr[4], rdiv[4], arr[4];
#pragma unroll
        for (int i = 0; i < 4; i++) {
            float rr = (float)(4 * ty + i);
            float cs = (rr + 1.f) * ts + 0.5f * (rr + 1.f) * (rr + 2.f);
            csr[i]  = cs;
            rdiv[i] = 1.f / (tri0 + cs);
            arr[i]  = tri0 * rdiv[i];
        }

        /* D: O = (Q @ W_avg)*a + (Q @ W_t)*(1-a) */
        float o[4][4];
        {
            float acc1[4][4] = {}, acc2[4][4] = {};
            for (int k = 0; k < 64; k++) {
                float q0[4], wa0[4], wt0[4];
#pragma unroll
                for (int i = 0; i < 4; i++) q0[i] = Qs[(4 * ty + i) * STRIDE + k];
#pragma unroll
                for (int j = 0; j < 4; j++) {
                    wa0[j] = Wa[k * STRIDE + 4 * tx + j];
                    wt0[j] = Wt[k * STRIDE + 4 * tx + j];
                }
#pragma unroll
                for (int i = 0; i < 4; i++)
#pragma unroll
                    for (int j = 0; j < 4; j++) {
                        acc1[i][j] += q0[i] * wa0[j];
                        acc2[i][j] += q0[i] * wt0[j];
                    }
            }
#pragma unroll
            for (int i = 0; i < 4; i++)
#pragma unroll
                for (int j = 0; j < 4; j++)
                    o[i][j] = acc1[i][j] * arr[i] + acc2[i][j] * (1.f - arr[i]);
        }

        /* E: QK = Q @ K^T (into Ts) */
        {
            float acc[4][4] = {};
            for (int k = 0; k < 64; k++) {
                float q0[4], k0[4];
#pragma unroll
                for (int i = 0; i < 4; i++) q0[i] = Qs[(4 * ty + i) * STRIDE + k];
#pragma unroll
                for (int j = 0; j < 4; j++) k0[j] = Ks[(4 * tx + j) * STRIDE + k];
#pragma unroll
                for (int i = 0; i < 4; i++)
#pragma unroll
                    for (int j = 0; j < 4; j++) acc[i][j] += q0[i] * k0[j];
            }
            __syncthreads();
#pragma unroll
            for (int i = 0; i < 4; i++)
#pragma unroll
                for (int j = 0; j < 4; j++)
                    Ts[(4 * ty + i) * STRIDE + 4 * tx + j] = acc[i][j];
        }
        __syncthreads();

        /* F: O += (T_mat o QK) @ U */
        {
            for (int kp = 0; kp < 64; kp++) {
                float kf = (float)kp;
                float csk_m = kf * ts + 0.5f * kf * (kf + 1.f);
                float u0[4];
#pragma unroll
                for (int j = 0; j < 4; j++) u0[j] = Us[kp * STRIDE + 4 * tx + j];
#pragma unroll
                for (int i = 0; i < 4; i++) {
                    float num  = csr[i] - csk_m;
                    float sfac = (num >= 0.f) ? num * rdiv[i] : 0.f;
                    float sv   = sfac * Ts[(4 * ty + i) * STRIDE + kp];
#pragma unroll
                    for (int j = 0; j < 4; j++) o[i][j] += sv * u0[j];
                }
            }
        }

        /* G: O -> smem, fused RMS norm, store split halves for final GEMM */
#pragma unroll
        for (int i = 0; i < 4; i++)
#pragma unroll
            for (int j = 0; j < 4; j++)
                Bss[(4 * ty + i) * STRIDE + 4 * tx + j] = o[i][j];
        __syncthreads();
        {
            const int r = tid >> 2, seg = tid & 3;
            const float* br = Bss + r * STRIDE + seg * 16;
            float ssum = 0.f;
#pragma unroll
            for (int t = 0; t < 16; t++) ssum += br[t] * br[t];
            ssum += __shfl_down_sync(0xffffffffu, ssum, 2);
            ssum += __shfl_down_sync(0xffffffffu, ssum, 1);
            ssum = __shfl_sync(0xffffffffu, ssum, (tid & 31) & ~3);
            float scale = rsqrtf(ssum * (1.f / 64.f) + 1e-6f);
            int l = chunk * 64 + r;
            size_t ob = ((size_t)(b * L_DIM + l)) * D_MODEL + h * D_HEAD + seg * 16;
#pragma unroll
            for (int t = 0; t < 16; t++) {
                float val = br[t] * scale * rw[seg * 16 + t];
                __half hv = __float2half_rn(val);
                g_oh[ob + t] = hv;
                g_ol[ob + t] = __float2half_rn(val - __half2float(hv));
            }
        }

        /* H: W updates */
        {
            float p1[4][4] = {}, p2[4][4] = {};
            for (int r = 0; r < 64; r++) {
                float rr   = (float)r;
                float idxr = ts + rr + 1.f;
                float csrr = (rr + 1.f) * ts + 0.5f * (rr + 1.f) * (rr + 2.f);
                float wr   = (idxr + Ssum - csrr) / denw;
                float kv[4], uv[4], uw[4];
#pragma unroll
                for (int i = 0; i < 4; i++) kv[i] = Ks[r * STRIDE + 4 * ty + i];
#pragma unroll
                for (int j = 0; j < 4; j++) { uv[j] = Us[r * STRIDE + 4 * tx + j]; uw[j] = uv[j] * wr; }
#pragma unroll
                for (int i = 0; i < 4; i++)
#pragma unroll
                    for (int j = 0; j < 4; j++) {
                        p1[i][j] += kv[i] * uv[j];
                        p2[i][j] += kv[i] * uw[j];
                    }
            }
#pragma unroll
            for (int i = 0; i < 4; i++)
#pragma unroll
                for (int j = 0; j < 4; j++) {
                    int idx2 = (4 * ty + i) * STRIDE + 4 * tx + j;
                    float wold = Wt[idx2], waold = Wa[idx2];
                    Wa[idx2] = coef1 * waold + coef2 * wold + p2[i][j];
                    Wt[idx2] = wold + p1[i][j];
                }
        }
    }
}

/* ------------------------------- launcher ----------------------------------*/
extern "C" void kernel_launch(void* const* d_in, const int* in_sizes, int n_in,
                              void* d_out, int out_size)
{
    (void)in_sizes; (void)n_in; (void)out_size;
    const float* x     = (const float*)d_in[0];
    const float* Wk    = (const float*)d_in[1];
    const float* bk    = (const float*)d_in[2];
    const float* Wq    = (const float*)d_in[3];
    const float* bq    = (const float*)d_in[4];
    const float* Wv    = (const float*)d_in[5];
    const float* bv    = (const float*)d_in[6];
    const float* Wbeta = (const float*)d_in[7];
    const float* bbeta = (const float*)d_in[8];
    const float* ck    = (const float*)d_in[9];
    const float* cq    = (const float*)d_in[10];
    const float* cv    = (const float*)d_in[11];
    const float* rms_w = (const float*)d_in[12];
    const float* Wout  = (const float*)d_in[13];
    const float* bout  = (const float*)d_in[14];
    float* out = (float*)d_out;

    float *kpre, *qpre, *vpre;
    __half *xh, *xl, *oh, *ol, *wsh, *wsl;
    cudaGetSymbolAddress((void**)&kpre, g_kpre);
    cudaGetSymbolAddress((void**)&qpre, g_qpre);
    cudaGetSymbolAddress((void**)&vpre, g_vpre);
    cudaGetSymbolAddress((void**)&xh, g_xh);
    cudaGetSymbolAddress((void**)&xl, g_xl);
    cudaGetSymbolAddress((void**)&oh, g_oh);
    cudaGetSymbolAddress((void**)&ol, g_ol);
    cudaGetSymbolAddress((void**)&wsh, g_wsh);
    cudaGetSymbolAddress((void**)&wsl, g_wsl);

    /* pre-split X and the 4 weight matrices into fp16 hi/lo pairs */
    split_f2h<<<(ML * D_MODEL / 4 + 255) / 256, 256>>>(
        (const float4*)x, (uint2*)xh, (uint2*)xl, ML * D_MODEL / 4);
    split_f2h<<<(DD / 4 + 255) / 256, 256>>>(
        (const float4*)Wk, (uint2*)wsh, (uint2*)wsl, DD / 4);
    split_f2h<<<(DD / 4 + 255) / 256, 256>>>(
        (const float4*)Wq, (uint2*)(wsh + DD), (uint2*)(wsl + DD), DD / 4);
    split_f2h<<<(DD / 4 + 255) / 256, 256>>>(
        (const float4*)Wv, (uint2*)(wsh + 2 * DD), (uint2*)(wsl + 2 * DD), DD / 4);
    split_f2h<<<(DD / 4 + 255) / 256, 256>>>(
        (const float4*)Wout, (uint2*)(wsh + 3 * DD), (uint2*)(wsl + 3 * DD), DD / 4);

    cudaFuncSetAttribute(gemm_h3ld, cudaFuncAttributeMaxDynamicSharedMemorySize,
                         GSM_BYTES);

    dim3 gg(D_MODEL / 128, ML / 128);

    gemm_h3ld<<<gg, 256, GSM_BYTES>>>(xh, xl, wsh, wsl, bk, kpre,
                                      ML, D_MODEL, D_MODEL);
    gemm_h3ld<<<gg, 256, GSM_BYTES>>>(xh, xl, wsh + DD, wsl + DD, bq, qpre,
                                      ML, D_MODEL, D_MODEL);
    gemm_h3ld<<<gg, 256, GSM_BYTES>>>(xh, xl, wsh + 2 * DD, wsl + 2 * DD, bv, vpre,
                                      ML, D_MODEL, D_MODEL);

    prep_kernel<<<ML, 256>>>(x, Wbeta, bbeta, ck, cq, cv);

    size_t smem_bytes = SMEM_FLOATS * sizeof(float);
    cudaFuncSetAttribute(delta_kernel, cudaFuncAttributeMaxDynamicSharedMemorySize,
                         (int)smem_bytes);
    delta_kernel<<<N_PAIR, 256, smem_bytes>>>(rms_w);

    gemm_h3ld<<<gg, 256, GSM_BYTES>>>(oh, ol, wsh + 3 * DD, wsl + 3 * DD, bout, out,
                                      ML, D_MODEL, D_MODEL);
}

// round 6
// speedup vs baseline: 1.6711x; 1.1877x over previous
#include <cuda_runtime.h>
#include <cuda_fp16.h>
#include <math.h>
#include <stdint.h>

#define B_DIM   4
#define L_DIM   2048
#define D_MODEL 1024
#define N_HEADS 16
#define D_HEAD  64
#define ML      (B_DIM * L_DIM)          /* 8192 rows */
#define N_PAIR  (B_DIM * N_HEADS)        /* 64 scan lanes */
#define N_CHUNK (L_DIM / 64)             /* 32 chunks */
#define STRIDE  65                       /* delta smem row stride */
#define DD      (D_MODEL * D_MODEL)

/* ---------------- scratch (device globals; no runtime alloc) ---------------- */
__device__ float  g_kpre[ML * D_MODEL];
__device__ float  g_qpre[ML * D_MODEL];
__device__ float  g_vpre[ML * D_MODEL];
__device__ float  g_kn  [ML * D_MODEL];
__device__ float  g_qn  [ML * D_MODEL];
__device__ float  g_vs  [ML * D_MODEL];
__device__ float  g_bb  [ML * D_MODEL];
__device__ __half g_xh  [ML * D_MODEL];
__device__ __half g_xl  [ML * D_MODEL];
__device__ __half g_oh  [ML * D_MODEL];
__device__ __half g_ol  [ML * D_MODEL];
__device__ __half g_wsh [4 * DD];
__device__ __half g_wsl [4 * DD];

/* ---------------- fp32 -> (hi,lo) fp16 split, vectorized -------------------- */
__global__ __launch_bounds__(256) void split_f2h(
    const float4* __restrict__ src, uint2* __restrict__ hi,
    uint2* __restrict__ lo, int n4)
{
    int i = blockIdx.x * blockDim.x + threadIdx.x;
    if (i >= n4) return;
    float4 v = src[i];
    __half2 h01 = __floats2half2_rn(v.x, v.y);
    __half2 h23 = __floats2half2_rn(v.z, v.w);
    __half2 l01 = __floats2half2_rn(v.x - __low2float(h01), v.y - __high2float(h01));
    __half2 l23 = __floats2half2_rn(v.z - __low2float(h23), v.w - __high2float(h23));
    hi[i] = make_uint2(*(uint32_t*)&h01, *(uint32_t*)&h23);
    lo[i] = make_uint2(*(uint32_t*)&l01, *(uint32_t*)&l23);
}

/* =================== tensor-core GEMM (pre-split 3x FP16) ===================
   Y[M,N] = (Ah+Al)[M,K] @ (Bh+Bl)[N,K]^T + bias, fp32 accumulate.
   CTA tile 128x64x32, 8 warps (32x32 each) -> ~85 regs -> 3 CTAs/SM.
   cp.async double buffer, ldmatrix fragments, smem stride 40 halves.        */

#define HS      40
#define STG_B   30720                     /* (128+128+64+64) rows * 80 B */
#define AH_OFF  0
#define AL_OFF  10240
#define BH_OFF  20480
#define BL_OFF  25600
#define GSM_BYTES (2 * STG_B)             /* 61440 */

__device__ __forceinline__ uint32_t smem_u32(const void* p) {
    uint32_t a;
    asm("{ .reg .u64 t; cvta.to.shared.u64 t, %1; cvt.u32.u64 %0, t; }"
        : "=r"(a) : "l"(p));
    return a;
}

#define LDSM_X4(r, a)                                                         \
    asm volatile("ldmatrix.sync.aligned.m8n8.x4.shared.b16 "                  \
                 "{%0,%1,%2,%3}, [%4];"                                       \
                 : "=r"((r)[0]), "=r"((r)[1]), "=r"((r)[2]), "=r"((r)[3])     \
                 : "r"(a))

#define MMA_F16B(d, a, b0, b1)                                                \
    asm volatile(                                                             \
        "mma.sync.aligned.m16n8k16.row.col.f32.f16.f16.f32 "                  \
        "{%0,%1,%2,%3}, {%4,%5,%6,%7}, {%8,%9}, {%0,%1,%2,%3};"               \
        : "+f"(d[0]), "+f"(d[1]), "+f"(d[2]), "+f"(d[3])                      \
        : "r"(a[0]), "r"(a[1]), "r"(a[2]), "r"(a[3]), "r"(b0), "r"(b1))

#define CP_ASYNC16(sa, gp)                                                    \
    asm volatile("cp.async.cg.shared.global [%0], [%1], 16;"                  \
                 :: "r"(sa), "l"(gp))

__global__ __launch_bounds__(256, 3) void gemm_h3b(
    const __half* __restrict__ Ahg, const __half* __restrict__ Alg,
    const __half* __restrict__ Bhg, const __half* __restrict__ Blg,
    const float* __restrict__ bias, float* __restrict__ Y,
    int M, int N, int K)
{
    extern __shared__ char smg[];
    const uint32_t sbase = smem_u32(smg);

    const int tid = threadIdx.x;
    const int bm = blockIdx.y * 128, bn = blockIdx.x * 64;
    const int lane = tid & 31, w = tid >> 5;
    const int wm = (w >> 1) * 32, wn = (w & 1) * 32;
    const int g = lane >> 2, tg = lane & 3;

    const int arow = (lane & 7) + ((lane >> 3) & 1) * 8;
    const int acol = (lane >> 4) * 8;
    const int brow = ((lane >> 4) & 1) * 8 + (lane & 7);
    const int bcol = ((lane >> 3) & 1) * 8;

    const int r4 = tid >> 2, c4 = tid & 3;
    const uint32_t so = r4 * 80 + c4 * 16;

    float acc[2][4][4];
#pragma unroll
    for (int mt = 0; mt < 2; mt++)
#pragma unroll
        for (int nt = 0; nt < 4; nt++)
#pragma unroll
            for (int e = 0; e < 4; e++) acc[mt][nt][e] = 0.f;

    const int n_tiles = K >> 5;

#define LOAD_TILE(t) do {                                                     \
        const uint32_t _sb = sbase + ((t) & 1) * STG_B;                       \
        const int _kb = (t) << 5;                                             \
        const size_t _ga0 = (size_t)(bm + r4) * K + _kb + c4 * 8;             \
        const size_t _ga1 = (size_t)(bm + 64 + r4) * K + _kb + c4 * 8;        \
        const size_t _gb0 = (size_t)(bn + r4) * K + _kb + c4 * 8;             \
        CP_ASYNC16(_sb + AH_OFF + so,           Ahg + _ga0);                  \
        CP_ASYNC16(_sb + AH_OFF + so + 5120,    Ahg + _ga1);                  \
        CP_ASYNC16(_sb + AL_OFF + so,           Alg + _ga0);                  \
        CP_ASYNC16(_sb + AL_OFF + so + 5120,    Alg + _ga1);                  \
        CP_ASYNC16(_sb + BH_OFF + so,           Bhg + _gb0);                  \
        CP_ASYNC16(_sb + BL_OFF + so,           Blg + _gb0);                  \
        asm volatile("cp.async.commit_group;");                               \
    } while (0)

    LOAD_TILE(0);

    for (int t = 0; t < n_tiles; t++) {
        if (t + 1 < n_tiles) {
            LOAD_TILE(t + 1);
            asm volatile("cp.async.wait_group 1;");
        } else {
            asm volatile("cp.async.wait_group 0;");
        }
        __syncthreads();

        const uint32_t sb = sbase + (t & 1) * STG_B;
#pragma unroll
        for (int kk = 0; kk < 2; kk++) {
            const int kc = kk * 16;
            uint32_t ah[2][4], al[2][4], bh[2][4], bl[2][4];
#pragma unroll
            for (int mt = 0; mt < 2; mt++) {
                uint32_t ad = sb + AH_OFF +
                              ((wm + mt * 16 + arow) * HS + kc + acol) * 2;
                LDSM_X4(ah[mt], ad);
                LDSM_X4(al[mt], ad + (AL_OFF - AH_OFF));
            }
#pragma unroll
            for (int a2 = 0; a2 < 2; a2++) {
                uint32_t bd = sb + BH_OFF +
                              ((wn + a2 * 16 + brow) * HS + kc + bcol) * 2;
                LDSM_X4(bh[a2], bd);
                LDSM_X4(bl[a2], bd + (BL_OFF - BH_OFF));
            }
#pragma unroll
            for (int mt = 0; mt < 2; mt++)
#pragma unroll
                for (int nt = 0; nt < 4; nt++) {
                    const int hi2 = nt >> 1, p = (nt & 1) * 2;
                    MMA_F16B(acc[mt][nt], ah[mt], bh[hi2][p], bh[hi2][p + 1]);
                    MMA_F16B(acc[mt][nt], ah[mt], bl[hi2][p], bl[hi2][p + 1]);
                    MMA_F16B(acc[mt][nt], al[mt], bh[hi2][p], bh[hi2][p + 1]);
                }
        }
        __syncthreads();
    }
#undef LOAD_TILE

#pragma unroll
    for (int mt = 0; mt < 2; mt++) {
        const int row = bm + wm + mt * 16 + g;
#pragma unroll
        for (int nt = 0; nt < 4; nt++) {
            const int col = bn + wn + nt * 8 + tg * 2;
            const float b0 = bias[col], b1 = bias[col + 1];
            float2 v0 = make_float2(acc[mt][nt][0] + b0, acc[mt][nt][1] + b1);
            float2 v1 = make_float2(acc[mt][nt][2] + b0, acc[mt][nt][3] + b1);
            *(float2*)(Y + (size_t)row * N + col) = v0;
            *(float2*)(Y + (size_t)(row + 8) * N + col) = v1;
        }
    }
}

/* -------- fused: short-conv(K=4) + beta + silu + L2 norm -------------------- */
__global__ __launch_bounds__(256) void prep_kernel(
    const float* __restrict__ x,
    const float* __restrict__ Wbeta, const float* __restrict__ bbeta,
    const float* __restrict__ ck, const float* __restrict__ cq,
    const float* __restrict__ cv)
{
    __shared__ float xrow[D_MODEL];
    __shared__ float ks[D_MODEL], qs[D_MODEL], vs[D_MODEL];
    __shared__ float eta_s[N_HEADS], kn_s[N_HEADS], qn_s[N_HEADS];

    const int bl = blockIdx.x;
    const int b = bl >> 11;
    const int l = bl & 2047;
    const int tid = threadIdx.x;

    for (int d = tid; d < D_MODEL; d += 256) xrow[d] = x[(size_t)bl * D_MODEL + d];

    for (int d = tid; d < D_MODEL; d += 256) {
        float ak = 0.f, aq = 0.f, av = 0.f;
#pragma unroll
        for (int j = 0; j < 4; j++) {
            int ls = l + j - 3;
            if (ls >= 0) {
                size_t idx = ((size_t)b * L_DIM + ls) * D_MODEL + d;
                ak += g_kpre[idx] * ck[d * 4 + j];
                aq += g_qpre[idx] * cq[d * 4 + j];
                av += g_vpre[idx] * cv[d * 4 + j];
            }
        }
        ks[d] = ak; qs[d] = aq; vs[d] = av;
    }
    __syncthreads();

    const int warp = tid >> 5, lane = tid & 31;
    for (int h = warp; h < N_HEADS; h += 8) {
        float s = 0.f;
        const float* wb = Wbeta + h * D_MODEL;
        for (int k = lane; k < D_MODEL; k += 32) s += xrow[k] * wb[k];
#pragma unroll
        for (int o = 16; o > 0; o >>= 1) s += __shfl_down_sync(0xffffffffu, s, o);
        if (lane == 0) eta_s[h] = 1.f / (1.f + __expf(-(s + bbeta[h])));
    }
    for (int h = warp; h < N_HEADS; h += 8) {
        float a0 = ks[h * 64 + lane], a1 = ks[h * 64 + 32 + lane];
        float sk = a0 * a0 + a1 * a1;
        float q0 = qs[h * 64 + lane], q1 = qs[h * 64 + 32 + lane];
        float sq = q0 * q0 + q1 * q1;
#pragma unroll
        for (int o = 16; o > 0; o >>= 1) {
            sk += __shfl_down_sync(0xffffffffu, sk, o);
            sq += __shfl_down_sync(0xffffffffu, sq, o);
        }
        if (lane == 0) { kn_s[h] = sqrtf(sk); qn_s[h] = sqrtf(sq); }
    }
    __syncthreads();

    for (int d = tid; d < D_MODEL; d += 256) {
        int h = d >> 6;
        float kn = ks[d] / (kn_s[h] + 1e-6f);
        float qn = qs[d] / (qn_s[h] + 1e-6f);
        float vv = vs[d];
        float sv = vv / (1.f + __expf(-vv));
        float e = eta_s[h];
        size_t base = (((size_t)(b * N_HEADS + h)) * L_DIM + l) * D_HEAD + (d & 63);
        g_kn[base] = kn;
        g_qn[base] = qn;
        g_vs[base] = e * sv;
        g_bb[base] = e * kn;
    }
}

/* ---------------- chunked o2b weighted delta-rule scan ----------------------
   forward substitution now blocked (8x8 diagonal-block inverses): 18 syncs
   per chunk instead of 126. ---------------------------------------------- */
#define SMEM_FLOATS (7 * 64 * STRIDE + 64 + 512 + 512)

__global__ __launch_bounds__(256) void delta_kernel(const float* __restrict__ rms_w)
{
    extern __shared__ float smd[];
    float* Wt   = smd;
    float* Wa   = Wt  + 64 * STRIDE;
    float* Ks   = Wa  + 64 * STRIDE;
    float* Qs   = Ks  + 64 * STRIDE;
    float* Us   = Qs  + 64 * STRIDE;
    float* Bss  = Us  + 64 * STRIDE;
    float* Ts   = Bss + 64 * STRIDE;
    float* rw   = Ts  + 64 * STRIDE;   /* 64  */
    float* invD = rw + 64;             /* 512: 8 blocks x 8x8 */
    float* Mb   = invD + 512;          /* 512: 8 x 64 staging */

    const int tid = threadIdx.x;
    const int tx = tid & 15;
    const int ty = tid >> 4;
    const int pair = blockIdx.x;
    const int b = pair >> 4, h = pair & 15;

    for (int i = tid; i < 64 * STRIDE; i += 256) { Wt[i] = 0.f; Wa[i] = 0.f; }
    if (tid < 64) rw[tid] = rms_w[tid];

    const size_t pbase = (size_t)pair * L_DIM * D_HEAD;

    for (int chunk = 0; chunk < N_CHUNK; chunk++) {
        __syncthreads();
        const size_t cb = pbase + (size_t)chunk * 64 * D_HEAD;
        for (int i2 = tid; i2 < 4096; i2 += 256) {
            int s = (i2 >> 6) * STRIDE + (i2 & 63);
            Ks[s]  = g_kn[cb + i2];
            Qs[s]  = g_qn[cb + i2];
            Us[s]  = g_vs[cb + i2];
            Bss[s] = g_bb[cb + i2];
        }
        __syncthreads();

        const float ts    = (float)(chunk * 64);
        const float tri0  = 0.5f * (1.f + ts) * ts;
        const float denw  = 0.5f * (65.f + ts) * (64.f + ts);
        const float Ssum  = 64.f * ts + 2080.f;
        const float coef1 = (ts / (ts + 64.f)) * ((1.f + ts) / (ts + 65.f));
        const float coef2 = (64.f / (ts + 64.f)) * ((2.f * ts + 65.f) / (ts + 65.f));

        /* A: T = strict_tril(B @ K^T) */
        {
            float acc[4][4] = {};
            for (int k = 0; k < 64; k++) {
                float a0[4], b0[4];
#pragma unroll
                for (int i = 0; i < 4; i++) a0[i] = Bss[(4 * ty + i) * STRIDE + k];
#pragma unroll
                for (int j = 0; j < 4; j++) b0[j] = Ks[(4 * tx + j) * STRIDE + k];
#pragma unroll
                for (int i = 0; i < 4; i++)
#pragma unroll
                    for (int j = 0; j < 4; j++) acc[i][j] += a0[i] * b0[j];
            }
#pragma unroll
            for (int i = 0; i < 4; i++)
#pragma unroll
                for (int j = 0; j < 4; j++) {
                    int r = 4 * ty + i, c = 4 * tx + j;
                    Ts[r * STRIDE + c] = (r > c) ? acc[i][j] : 0.f;
                }
        }
        __syncthreads();

        /* B: RHS = V - B @ W_t */
        {
            float acc[4][4] = {};
            for (int k = 0; k < 64; k++) {
                float a0[4], w0[4];
#pragma unroll
                for (int i = 0; i < 4; i++) a0[i] = Bss[(4 * ty + i) * STRIDE + k];
#pragma unroll
                for (int j = 0; j < 4; j++) w0[j] = Wt[k * STRIDE + 4 * tx + j];
#pragma unroll
                for (int i = 0; i < 4; i++)
#pragma unroll
                    for (int j = 0; j < 4; j++) acc[i][j] += a0[i] * w0[j];
            }
#pragma unroll
            for (int i = 0; i < 4; i++)
#pragma unroll
                for (int j = 0; j < 4; j++)
                    Us[(4 * ty + i) * STRIDE + 4 * tx + j] -= acc[i][j];
        }

        /* C0: invert the 8 unit-lower 8x8 diagonal blocks of (I+T) */
        if (tid < 64) {
            const int blk = tid >> 3, c = tid & 7;
            const int r0 = blk * 8;
            float xcol[8];
#pragma unroll
            for (int r = 0; r < 8; r++) {
                float s = (r == c) ? 1.f : 0.f;
                for (int k2 = c; k2 < r; k2++)
                    s -= Ts[(r0 + r) * STRIDE + r0 + k2] * xcol[k2];
                xcol[r] = s;
            }
#pragma unroll
            for (int r = 0; r < 8; r++) invD[(r0 + r) * 8 + c] = xcol[r];
        }
        __syncthreads();

        /* C: blocked forward substitution  (I+T) U = RHS */
        {
            const int cc = tid & 63;
            const int rbase = tid >> 6;       /* 0..3 */
            for (int ib = 0; ib < 8; ib++) {
                const int r0 = ib * 8;
#pragma unroll
                for (int hf = 0; hf < 2; hf++) {
                    const int r = rbase + hf * 4;
                    float s = 0.f;
                    for (int j = 0; j < r0; j++)
                        s += Ts[(r0 + r) * STRIDE + j] * Us[j * STRIDE + cc];
                    Mb[r * 64 + cc] = Us[(r0 + r) * STRIDE + cc] - s;
                }
                __syncthreads();
#pragma unroll
                for (int hf = 0; hf < 2; hf++) {
                    const int r = rbase + hf * 4;
                    float s = Mb[r * 64 + cc];
                    for (int k2 = 0; k2 < r; k2++)
                        s += invD[(r0 + r) * 8 + k2] * Mb[k2 * 64 + cc];
                    Us[(r0 + r) * STRIDE + cc] = s;
                }
                __syncthreads();
            }
        }

        float csr[4], rdiv[4], arr[4];
#pragma unroll
        for (int i = 0; i < 4; i++) {
            float rr = (float)(4 * ty + i);
            float cs = (rr + 1.f) * ts + 0.5f * (rr + 1.f) * (rr + 2.f);
            csr[i]  = cs;
            rdiv[i] = 1.f / (tri0 + cs);
            arr[i]  = tri0 * rdiv[i];
        }

        /* D: O = (Q @ W_avg)*a + (Q @ W_t)*(1-a) */
        float o[4][4];
        {
            float acc1[4][4] = {}, acc2[4][4] = {};
            for (int k = 0; k < 64; k++) {
                float q0[4], wa0[4], wt0[4];
#pragma unroll
                for (int i = 0; i < 4; i++) q0[i] = Qs[(4 * ty + i) * STRIDE + k];
#pragma unroll
                for (int j = 0; j < 4; j++) {
                    wa0[j] = Wa[k * STRIDE + 4 * tx + j];
                    wt0[j] = Wt[k * STRIDE + 4 * tx + j];
                }
#pragma unroll
                for (int i = 0; i < 4; i++)
#pragma unroll
                    for (int j = 0; j < 4; j++) {
                        acc1[i][j] += q0[i] * wa0[j];
                        acc2[i][j] += q0[i] * wt0[j];
                    }
            }
#pragma unroll
            for (int i = 0; i < 4; i++)
#pragma unroll
                for (int j = 0; j < 4; j++)
                    o[i][j] = acc1[i][j] * arr[i] + acc2[i][j] * (1.f - arr[i]);
        }

        /* E: QK = Q @ K^T (into Ts) */
        {
            float acc[4][4] = {};
            for (int k = 0; k < 64; k++) {
                float q0[4], k0[4];
#pragma unroll
                for (int i = 0; i < 4; i++) q0[i] = Qs[(4 * ty + i) * STRIDE + k];
#pragma unroll
                for (int j = 0; j < 4; j++) k0[j] = Ks[(4 * tx + j) * STRIDE + k];
#pragma unroll
                for (int i = 0; i < 4; i++)
#pragma unroll
                    for (int j = 0; j < 4; j++) acc[i][j] += q0[i] * k0[j];
            }
            __syncthreads();
#pragma unroll
            for (int i = 0; i < 4; i++)
#pragma unroll
                for (int j = 0; j < 4; j++)
                    Ts[(4 * ty + i) * STRIDE + 4 * tx + j] = acc[i][j];
        }
        __syncthreads();

        /* F: O += (T_mat o QK) @ U */
        {
            for (int kp = 0; kp < 64; kp++) {
                float kf = (float)kp;
                float csk_m = kf * ts + 0.5f * kf * (kf + 1.f);
                float u0[4];
#pragma unroll
                for (int j = 0; j < 4; j++) u0[j] = Us[kp * STRIDE + 4 * tx + j];
#pragma unroll
                for (int i = 0; i < 4; i++) {
                    float num  = csr[i] - csk_m;
                    float sfac = (num >= 0.f) ? num * rdiv[i] : 0.f;
                    float sv   = sfac * Ts[(4 * ty + i) * STRIDE + kp];
#pragma unroll
                    for (int j = 0; j < 4; j++) o[i][j] += sv * u0[j];
                }
            }
        }

        /* G: O -> smem, fused RMS norm, store split halves for final GEMM */
#pragma unroll
        for (int i = 0; i < 4; i++)
#pragma unroll
            for (int j = 0; j < 4; j++)
                Bss[(4 * ty + i) * STRIDE + 4 * tx + j] = o[i][j];
        __syncthreads();
        {
            const int r = tid >> 2, seg = tid & 3;
            const float* br = Bss + r * STRIDE + seg * 16;
            float ssum = 0.f;
#pragma unroll
            for (int t = 0; t < 16; t++) ssum += br[t] * br[t];
            ssum += __shfl_down_sync(0xffffffffu, ssum, 2);
            ssum += __shfl_down_sync(0xffffffffu, ssum, 1);
            ssum = __shfl_sync(0xffffffffu, ssum, (tid & 31) & ~3);
            float scale = rsqrtf(ssum * (1.f / 64.f) + 1e-6f);
            int l = chunk * 64 + r;
            size_t ob = ((size_t)(b * L_DIM + l)) * D_MODEL + h * D_HEAD + seg * 16;
#pragma unroll
            for (int t = 0; t < 16; t++) {
                float val = br[t] * scale * rw[seg * 16 + t];
                __half hv = __float2half_rn(val);
                g_oh[ob + t] = hv;
                g_ol[ob + t] = __float2half_rn(val - __half2float(hv));
            }
        }

        /* H: W updates */
        {
            float p1[4][4] = {}, p2[4][4] = {};
            for (int r = 0; r < 64; r++) {
                float rr   = (float)r;
                float idxr = ts + rr + 1.f;
                float csrr = (rr + 1.f) * ts + 0.5f * (rr + 1.f) * (rr + 2.f);
                float wr   = (idxr + Ssum - csrr) / denw;
                float kv[4], uv[4], uw[4];
#pragma unroll
                for (int i = 0; i < 4; i++) kv[i] = Ks[r * STRIDE + 4 * ty + i];
#pragma unroll
                for (int j = 0; j < 4; j++) { uv[j] = Us[r * STRIDE + 4 * tx + j]; uw[j] = uv[j] * wr; }
#pragma unroll
                for (int i = 0; i < 4; i++)
#pragma unroll
                    for (int j = 0; j < 4; j++) {
                        p1[i][j] += kv[i] * uv[j];
                        p2[i][j] += kv[i] * uw[j];
                    }
            }
#pragma unroll
            for (int i = 0; i < 4; i++)
#pragma unroll
                for (int j = 0; j < 4; j++) {
                    int idx2 = (4 * ty + i) * STRIDE + 4 * tx + j;
                    float wold = Wt[idx2], waold = Wa[idx2];
                    Wa[idx2] = coef1 * waold + coef2 * wold + p2[i][j];
                    Wt[idx2] = wold + p1[i][j];
                }
        }
    }
}

/* ------------------------------- launcher ----------------------------------*/
extern "C" void kernel_launch(void* const* d_in, const int* in_sizes, int n_in,
                              void* d_out, int out_size)
{
    (void)in_sizes; (void)n_in; (void)out_size;
    const float* x     = (const float*)d_in[0];
    const float* Wk    = (const float*)d_in[1];
    const float* bk    = (const float*)d_in[2];
    const float* Wq    = (const float*)d_in[3];
    const float* bq    = (const float*)d_in[4];
    const float* Wv    = (const float*)d_in[5];
    const float* bv    = (const float*)d_in[6];
    const float* Wbeta = (const float*)d_in[7];
    const float* bbeta = (const float*)d_in[8];
    const float* ck    = (const float*)d_in[9];
    const float* cq    = (const float*)d_in[10];
    const float* cv    = (const float*)d_in[11];
    const float* rms_w = (const float*)d_in[12];
    const float* Wout  = (const float*)d_in[13];
    const float* bout  = (const float*)d_in[14];
    float* out = (float*)d_out;

    float *kpre, *qpre, *vpre;
    __half *xh, *xl, *oh, *ol, *wsh, *wsl;
    cudaGetSymbolAddress((void**)&kpre, g_kpre);
    cudaGetSymbolAddress((void**)&qpre, g_qpre);
    cudaGetSymbolAddress((void**)&vpre, g_vpre);
    cudaGetSymbolAddress((void**)&xh, g_xh);
    cudaGetSymbolAddress((void**)&xl, g_xl);
    cudaGetSymbolAddress((void**)&oh, g_oh);
    cudaGetSymbolAddress((void**)&ol, g_ol);
    cudaGetSymbolAddress((void**)&wsh, g_wsh);
    cudaGetSymbolAddress((void**)&wsl, g_wsl);

    split_f2h<<<(ML * D_MODEL / 4 + 255) / 256, 256>>>(
        (const float4*)x, (uint2*)xh, (uint2*)xl, ML * D_MODEL / 4);
    split_f2h<<<(DD / 4 + 255) / 256, 256>>>(
        (const float4*)Wk, (uint2*)wsh, (uint2*)wsl, DD / 4);
    split_f2h<<<(DD / 4 + 255) / 256, 256>>>(
        (const float4*)Wq, (uint2*)(wsh + DD), (uint2*)(wsl + DD), DD / 4);
    split_f2h<<<(DD / 4 + 255) / 256, 256>>>(
        (const float4*)Wv, (uint2*)(wsh + 2 * DD), (uint2*)(wsl + 2 * DD), DD / 4);
    split_f2h<<<(DD / 4 + 255) / 256, 256>>>(
        (const float4*)Wout, (uint2*)(wsh + 3 * DD), (uint2*)(wsl + 3 * DD), DD / 4);

    cudaFuncSetAttribute(gemm_h3b, cudaFuncAttributeMaxDynamicSharedMemorySize,
                         GSM_BYTES);

    dim3 gg(D_MODEL / 64, ML / 128);

    gemm_h3b<<<gg, 256, GSM_BYTES>>>(xh, xl, wsh, wsl, bk, kpre,
                                     ML, D_MODEL, D_MODEL);
    gemm_h3b<<<gg, 256, GSM_BYTES>>>(xh, xl, wsh + DD, wsl + DD, bq, qpre,
                                     ML, D_MODEL, D_MODEL);
    gemm_h3b<<<gg, 256, GSM_BYTES>>>(xh, xl, wsh + 2 * DD, wsl + 2 * DD, bv, vpre,
                                     ML, D_MODEL, D_MODEL);

    prep_kernel<<<ML, 256>>>(x, Wbeta, bbeta, ck, cq, cv);

    size_t smem_bytes = SMEM_FLOATS * sizeof(float);
    cudaFuncSetAttribute(delta_kernel, cudaFuncAttributeMaxDynamicSharedMemorySize,
                         (int)smem_bytes);
    delta_kernel<<<N_PAIR, 256, smem_bytes>>>(rms_w);

    gemm_h3b<<<gg, 256, GSM_BYTES>>>(oh, ol, wsh + 3 * DD, wsl + 3 * DD, bout, out,
                                     ML, D_MODEL, D_MODEL);
}

// round 7
// speedup vs baseline: 2.2055x; 1.3198x over previous
#include <cuda_runtime.h>
#include <cuda_fp16.h>
#include <math.h>
#include <stdint.h>

#define B_DIM   4
#define L_DIM   2048
#define D_MODEL 1024
#define N_HEADS 16
#define D_HEAD  64
#define ML      (B_DIM * L_DIM)          /* 8192 rows */
#define N_PAIR  (B_DIM * N_HEADS)        /* 64 scan lanes */
#define N_CHUNK (L_DIM / 64)             /* 32 chunks */
#define DD      (D_MODEL * D_MODEL)
#define FS      65                       /* full-array smem stride */
#define HSX     33                       /* half-array smem stride */

/* ---------------- scratch (device globals; no runtime alloc) ---------------- */
__device__ float  g_kpre[ML * D_MODEL];
__device__ float  g_qpre[ML * D_MODEL];
__device__ float  g_vpre[ML * D_MODEL];
__device__ float  g_kn  [ML * D_MODEL];
__device__ float  g_qn  [ML * D_MODEL];
__device__ float  g_vs  [ML * D_MODEL];
__device__ float  g_bb  [ML * D_MODEL];
__device__ float  g_o   [ML * D_MODEL];
__device__ __half g_xh  [ML * D_MODEL];
__device__ __half g_xl  [ML * D_MODEL];
__device__ __half g_oh  [ML * D_MODEL];
__device__ __half g_ol  [ML * D_MODEL];
__device__ __half g_wsh [4 * DD];
__device__ __half g_wsl [4 * DD];

/* ---------------- fp32 -> (hi,lo) fp16 split, vectorized -------------------- */
__global__ __launch_bounds__(256) void split_f2h(
    const float4* __restrict__ src, uint2* __restrict__ hi,
    uint2* __restrict__ lo, int n4)
{
    int i = blockIdx.x * blockDim.x + threadIdx.x;
    if (i >= n4) return;
    float4 v = src[i];
    __half2 h01 = __floats2half2_rn(v.x, v.y);
    __half2 h23 = __floats2half2_rn(v.z, v.w);
    __half2 l01 = __floats2half2_rn(v.x - __low2float(h01), v.y - __high2float(h01));
    __half2 l23 = __floats2half2_rn(v.z - __low2float(h23), v.w - __high2float(h23));
    hi[i] = make_uint2(*(uint32_t*)&h01, *(uint32_t*)&h23);
    lo[i] = make_uint2(*(uint32_t*)&l01, *(uint32_t*)&l23);
}

/* =================== tensor-core GEMM machinery (3x FP16) =================== */
#define HS      40
#define STG_B   30720
#define AH_OFF  0
#define AL_OFF  10240
#define BH_OFF  20480
#define BL_OFF  25600
#define GSM_BYTES (2 * STG_B)

__device__ __forceinline__ uint32_t smem_u32(const void* p) {
    uint32_t a;
    asm("{ .reg .u64 t; cvta.to.shared.u64 t, %1; cvt.u32.u64 %0, t; }"
        : "=r"(a) : "l"(p));
    return a;
}

#define LDSM_X4(r, a)                                                         \
    asm volatile("ldmatrix.sync.aligned.m8n8.x4.shared.b16 "                  \
                 "{%0,%1,%2,%3}, [%4];"                                       \
                 : "=r"((r)[0]), "=r"((r)[1]), "=r"((r)[2]), "=r"((r)[3])     \
                 : "r"(a))

#define MMA_F16B(d, a, b0, b1)                                                \
    asm volatile(                                                             \
        "mma.sync.aligned.m16n8k16.row.col.f32.f16.f16.f32 "                  \
        "{%0,%1,%2,%3}, {%4,%5,%6,%7}, {%8,%9}, {%0,%1,%2,%3};"               \
        : "+f"(d[0]), "+f"(d[1]), "+f"(d[2]), "+f"(d[3])                      \
        : "r"(a[0]), "r"(a[1]), "r"(a[2]), "r"(a[3]), "r"(b0), "r"(b1))

#define CP_ASYNC16(sa, gp)                                                    \
    asm volatile("cp.async.cg.shared.global [%0], [%1], 16;"                  \
                 :: "r"(sa), "l"(gp))

/* shared mainloop body; bnG = global B-row base, Y/bias resolved by caller */
#define GEMM_BODY(bnG, Yptr, biasptr, Ncols)                                  \
    extern __shared__ char smg[];                                             \
    const uint32_t sbase = smem_u32(smg);                                     \
    const int tid = threadIdx.x;                                              \
    const int bm = blockIdx.y * 128;                                          \
    const int lane = tid & 31, w = tid >> 5;                                  \
    const int wm = (w >> 1) * 32, wn = (w & 1) * 32;                          \
    const int g = lane >> 2, tg = lane & 3;                                   \
    const int arow = (lane & 7) + ((lane >> 3) & 1) * 8;                      \
    const int acol = (lane >> 4) * 8;                                         \
    const int brow = ((lane >> 4) & 1) * 8 + (lane & 7);                      \
    const int bcol = ((lane >> 3) & 1) * 8;                                   \
    const int r4 = tid >> 2, c4 = tid & 3;                                    \
    const uint32_t so = r4 * 80 + c4 * 16;                                    \
    float acc[2][4][4];                                                       \
    _Pragma("unroll")                                                         \
    for (int mt = 0; mt < 2; mt++)                                            \
        _Pragma("unroll")                                                     \
        for (int nt = 0; nt < 4; nt++)                                        \
            _Pragma("unroll")                                                 \
            for (int e = 0; e < 4; e++) acc[mt][nt][e] = 0.f;                 \
    const int n_tiles = K >> 5;                                               \
    LOAD_TILE(0);                                                             \
    for (int t = 0; t < n_tiles; t++) {                                       \
        if (t + 1 < n_tiles) {                                                \
            LOAD_TILE(t + 1);                                                 \
            asm volatile("cp.async.wait_group 1;");                           \
        } else {                                                              \
            asm volatile("cp.async.wait_group 0;");                           \
        }                                                                     \
        __syncthreads();                                                      \
        const uint32_t sb = sbase + (t & 1) * STG_B;                          \
        _Pragma("unroll")                                                     \
        for (int kk = 0; kk < 2; kk++) {                                      \
            const int kc = kk * 16;                                           \
            uint32_t ah[2][4], al[2][4], bh[2][4], bl[2][4];                  \
            _Pragma("unroll")                                                 \
            for (int mt = 0; mt < 2; mt++) {                                  \
                uint32_t ad = sb + AH_OFF +                                   \
                              ((wm + mt * 16 + arow) * HS + kc + acol) * 2;   \
                LDSM_X4(ah[mt], ad);                                          \
                LDSM_X4(al[mt], ad + (AL_OFF - AH_OFF));                      \
            }                                                                 \
            _Pragma("unroll")                                                 \
            for (int a2 = 0; a2 < 2; a2++) {                                  \
                uint32_t bd = sb + BH_OFF +                                   \
                              ((wn + a2 * 16 + brow) * HS + kc + bcol) * 2;   \
                LDSM_X4(bh[a2], bd);                                          \
                LDSM_X4(bl[a2], bd + (BL_OFF - BH_OFF));                      \
            }                                                                 \
            _Pragma("unroll")                                                 \
            for (int mt = 0; mt < 2; mt++)                                    \
                _Pragma("unroll")                                             \
                for (int nt = 0; nt < 4; nt++) {                              \
                    const int hi2 = nt >> 1, p = (nt & 1) * 2;                \
                    MMA_F16B(acc[mt][nt], ah[mt], bh[hi2][p], bh[hi2][p+1]);  \
                    MMA_F16B(acc[mt][nt], ah[mt], bl[hi2][p], bl[hi2][p+1]);  \
                    MMA_F16B(acc[mt][nt], al[mt], bh[hi2][p], bh[hi2][p+1]);  \
                }                                                             \
        }                                                                     \
        __syncthreads();                                                      \
    }                                                                         \
    _Pragma("unroll")                                                         \
    for (int mt = 0; mt < 2; mt++) {                                          \
        const int row = bm + wm + mt * 16 + g;                                \
        _Pragma("unroll")                                                     \
        for (int nt = 0; nt < 4; nt++) {                                      \
            const int col = bnL + wn + nt * 8 + tg * 2;                       \
            const float b0 = (biasptr)[col], b1 = (biasptr)[col + 1];         \
            float2 v0 = make_float2(acc[mt][nt][0] + b0, acc[mt][nt][1] + b1);\
            float2 v1 = make_float2(acc[mt][nt][2] + b0, acc[mt][nt][3] + b1);\
            *(float2*)((Yptr) + (size_t)row * (Ncols) + col) = v0;            \
            *(float2*)((Yptr) + (size_t)(row + 8) * (Ncols) + col) = v1;      \
        }                                                                     \
    }

#define LOAD_TILE(t) do {                                                     \
        const uint32_t _sb = sbase + ((t) & 1) * STG_B;                       \
        const int _kb = (t) << 5;                                             \
        const size_t _ga0 = (size_t)(bm + r4) * K + _kb + c4 * 8;             \
        const size_t _ga1 = (size_t)(bm + 64 + r4) * K + _kb + c4 * 8;        \
        const size_t _gb0 = (size_t)(bnG + r4) * K + _kb + c4 * 8;            \
        CP_ASYNC16(_sb + AH_OFF + so,           Ahg + _ga0);                  \
        CP_ASYNC16(_sb + AH_OFF + so + 5120,    Ahg + _ga1);                  \
        CP_ASYNC16(_sb + AL_OFF + so,           Alg + _ga0);                  \
        CP_ASYNC16(_sb + AL_OFF + so + 5120,    Alg + _ga1);                  \
        CP_ASYNC16(_sb + BH_OFF + so,           Bhg + _gb0);                  \
        CP_ASYNC16(_sb + BL_OFF + so,           Blg + _gb0);                  \
        asm volatile("cp.async.commit_group;");                               \
    } while (0)

/* fused QKV GEMM: N=3072 over [Wk|Wq|Wv], three output buffers */
__global__ __launch_bounds__(256, 3) void gemm_qkv3(
    const __half* __restrict__ Ahg, const __half* __restrict__ Alg,
    const __half* __restrict__ Bhg, const __half* __restrict__ Blg,
    const float* __restrict__ bk, const float* __restrict__ bq,
    const float* __restrict__ bv,
    float* __restrict__ Yk, float* __restrict__ Yq, float* __restrict__ Yv,
    int M, int K)
{
    const int bnG = blockIdx.x * 64;
    const int seg = bnG >> 10;
    const int bnL = bnG & 1023;
    const float* bias = (seg == 0) ? bk : (seg == 1) ? bq : bv;
    float* Y = (seg == 0) ? Yk : (seg == 1) ? Yq : Yv;
    GEMM_BODY(bnG, Y, bias - bnL + bnL, D_MODEL)   /* bias indexed by local col */
}

/* single-output GEMM (final projection) */
__global__ __launch_bounds__(256, 3) void gemm_h3b(
    const __half* __restrict__ Ahg, const __half* __restrict__ Alg,
    const __half* __restrict__ Bhg, const __half* __restrict__ Blg,
    const float* __restrict__ bias, float* __restrict__ Y,
    int M, int N, int K)
{
    const int bnG = blockIdx.x * 64;
    const int bnL = bnG;
    GEMM_BODY(bnG, Y, bias, N)
}
#undef LOAD_TILE

/* -------- fused: short-conv(K=4) + beta + silu + L2 norm -------------------- */
__global__ __launch_bounds__(256) void prep_kernel(
    const float* __restrict__ x,
    const float* __restrict__ Wbeta, const float* __restrict__ bbeta,
    const float* __restrict__ ck, const float* __restrict__ cq,
    const float* __restrict__ cv)
{
    __shared__ float xrow[D_MODEL];
    __shared__ float ks[D_MODEL], qs[D_MODEL], vs[D_MODEL];
    __shared__ float eta_s[N_HEADS], kn_s[N_HEADS], qn_s[N_HEADS];

    const int bl = blockIdx.x;
    const int b = bl >> 11;
    const int l = bl & 2047;
    const int tid = threadIdx.x;

    for (int d = tid; d < D_MODEL; d += 256) xrow[d] = x[(size_t)bl * D_MODEL + d];

    for (int d = tid; d < D_MODEL; d += 256) {
        float ak = 0.f, aq = 0.f, av = 0.f;
#pragma unroll
        for (int j = 0; j < 4; j++) {
            int ls = l + j - 3;
            if (ls >= 0) {
                size_t idx = ((size_t)b * L_DIM + ls) * D_MODEL + d;
                ak += g_kpre[idx] * ck[d * 4 + j];
                aq += g_qpre[idx] * cq[d * 4 + j];
                av += g_vpre[idx] * cv[d * 4 + j];
            }
        }
        ks[d] = ak; qs[d] = aq; vs[d] = av;
    }
    __syncthreads();

    const int warp = tid >> 5, lane = tid & 31;
    for (int h = warp; h < N_HEADS; h += 8) {
        float s = 0.f;
        const float* wb = Wbeta + h * D_MODEL;
        for (int k = lane; k < D_MODEL; k += 32) s += xrow[k] * wb[k];
#pragma unroll
        for (int o = 16; o > 0; o >>= 1) s += __shfl_down_sync(0xffffffffu, s, o);
        if (lane == 0) eta_s[h] = 1.f / (1.f + __expf(-(s + bbeta[h])));
    }
    for (int h = warp; h < N_HEADS; h += 8) {
        float a0 = ks[h * 64 + lane], a1 = ks[h * 64 + 32 + lane];
        float sk = a0 * a0 + a1 * a1;
        float q0 = qs[h * 64 + lane], q1 = qs[h * 64 + 32 + lane];
        float sq = q0 * q0 + q1 * q1;
#pragma unroll
        for (int o = 16; o > 0; o >>= 1) {
            sk += __shfl_down_sync(0xffffffffu, sk, o);
            sq += __shfl_down_sync(0xffffffffu, sq, o);
        }
        if (lane == 0) { kn_s[h] = sqrtf(sk); qn_s[h] = sqrtf(sq); }
    }
    __syncthreads();

    for (int d = tid; d < D_MODEL; d += 256) {
        int h = d >> 6;
        float kn = ks[d] / (kn_s[h] + 1e-6f);
        float qn = qs[d] / (qn_s[h] + 1e-6f);
        float vv = vs[d];
        float sv = vv / (1.f + __expf(-vv));
        float e = eta_s[h];
        size_t base = (((size_t)(b * N_HEADS + h)) * L_DIM + l) * D_HEAD + (d & 63);
        g_kn[base] = kn;
        g_qn[base] = qn;
        g_vs[base] = e * sv;
        g_bb[base] = e * kn;
    }
}

/* ---------------- chunked o2b weighted delta-rule scan ----------------------
   COLUMN-SPLIT: 2 CTAs per (b,h) pair; each owns 32 of 64 head-dim columns
   of V/U/W_t/W_avg/O.  T and QK are recomputed redundantly per half.
   RMS norm deferred to rms_split kernel. ----------------------------------- */
#define SMEM_FLOATS (4 * 64 * FS + 3 * 64 * HSX + 512 + 256)

__global__ __launch_bounds__(256) void delta_kernel()
{
    extern __shared__ float smd[];
    float* Ks   = smd;                 /* 64 x 65 */
    float* Qs   = Ks + 64 * FS;
    float* Bss  = Qs + 64 * FS;
    float* Ts   = Bss + 64 * FS;
    float* Wt   = Ts + 64 * FS;        /* 64 x 33 */
    float* Wa   = Wt + 64 * HSX;
    float* Us   = Wa + 64 * HSX;
    float* invD = Us + 64 * HSX;       /* 512 */
    float* Mb   = invD + 512;          /* 8 x 32 */

    const int tid = threadIdx.x;
    const int tx = tid & 15;
    const int ty = tid >> 4;
    const int pair = blockIdx.x >> 1;
    const int half = blockIdx.x & 1;
    const int col0 = half * 32;
    const int b = pair >> 4, h = pair & 15;

    for (int i = tid; i < 64 * HSX; i += 256) { Wt[i] = 0.f; Wa[i] = 0.f; }

    const size_t pbase = (size_t)pair * L_DIM * D_HEAD;

    for (int chunk = 0; chunk < N_CHUNK; chunk++) {
        __syncthreads();
        const size_t cb = pbase + (size_t)chunk * 64 * D_HEAD;
        for (int i2 = tid; i2 < 4096; i2 += 256) {
            int s = (i2 >> 6) * FS + (i2 & 63);
            Ks[s]  = g_kn[cb + i2];
            Qs[s]  = g_qn[cb + i2];
            Bss[s] = g_bb[cb + i2];
        }
        for (int i2 = tid; i2 < 2048; i2 += 256) {
            int r = i2 >> 5, c = i2 & 31;
            Us[r * HSX + c] = g_vs[cb + r * 64 + col0 + c];
        }
        __syncthreads();

        const float ts    = (float)(chunk * 64);
        const float tri0  = 0.5f * (1.f + ts) * ts;
        const float denw  = 0.5f * (65.f + ts) * (64.f + ts);
        const float Ssum  = 64.f * ts + 2080.f;
        const float coef1 = (ts / (ts + 64.f)) * ((1.f + ts) / (ts + 65.f));
        const float coef2 = (64.f / (ts + 64.f)) * ((2.f * ts + 65.f) / (ts + 65.f));

        /* A: T = strict_tril(B @ K^T)  (full 64x64) */
        {
            float acc[4][4] = {};
            for (int k = 0; k < 64; k++) {
                float a0[4], b0[4];
#pragma unroll
                for (int i = 0; i < 4; i++) a0[i] = Bss[(4 * ty + i) * FS + k];
#pragma unroll
                for (int j = 0; j < 4; j++) b0[j] = Ks[(4 * tx + j) * FS + k];
#pragma unroll
                for (int i = 0; i < 4; i++)
#pragma unroll
                    for (int j = 0; j < 4; j++) acc[i][j] += a0[i] * b0[j];
            }
#pragma unroll
            for (int i = 0; i < 4; i++)
#pragma unroll
                for (int j = 0; j < 4; j++) {
                    int r = 4 * ty + i, c = 4 * tx + j;
                    Ts[r * FS + c] = (r > c) ? acc[i][j] : 0.f;
                }
        }
        __syncthreads();

        /* C0: invert the 8 unit-lower 8x8 diagonal blocks (threads 0-63) */
        if (tid < 64) {
            const int blk = tid >> 3, c = tid & 7;
            const int r0 = blk * 8;
            float xcol[8];
#pragma unroll
            for (int r = 0; r < 8; r++) {
                float s = (r == c) ? 1.f : 0.f;
                for (int k2 = c; k2 < r; k2++)
                    s -= Ts[(r0 + r) * FS + r0 + k2] * xcol[k2];
                xcol[r] = s;
            }
#pragma unroll
            for (int r = 0; r < 8; r++) invD[(r0 + r) * 8 + c] = xcol[r];
        }

        /* B: RHS = V - B @ W_t   (64 x 32, into Us) */
        {
            float acc[4][2] = {};
            for (int k = 0; k < 64; k++) {
                float a0[4], w0[2];
#pragma unroll
                for (int i = 0; i < 4; i++) a0[i] = Bss[(4 * ty + i) * FS + k];
#pragma unroll
                for (int j = 0; j < 2; j++) w0[j] = Wt[k * HSX + 2 * tx + j];
#pragma unroll
                for (int i = 0; i < 4; i++)
#pragma unroll
                    for (int j = 0; j < 2; j++) acc[i][j] += a0[i] * w0[j];
            }
#pragma unroll
            for (int i = 0; i < 4; i++)
#pragma unroll
                for (int j = 0; j < 2; j++)
                    Us[(4 * ty + i) * HSX + 2 * tx + j] -= acc[i][j];
        }
        __syncthreads();

        /* C: blocked forward substitution  (I+T) U = RHS  (32 cols) */
        {
            const int cc = tid & 31, rr = tid >> 5;   /* 8 rows x 32 cols */
            for (int ib = 0; ib < 8; ib++) {
                const int r0 = ib * 8;
                float s = 0.f;
                for (int j = 0; j < r0; j++)
                    s += Ts[(r0 + rr) * FS + j] * Us[j * HSX + cc];
                float rhs = Us[(r0 + rr) * HSX + cc] - s;
                Mb[rr * 32 + cc] = rhs;
                __syncthreads();
                s = rhs;
                for (int k2 = 0; k2 < rr; k2++)
                    s += invD[(r0 + rr) * 8 + k2] * Mb[k2 * 32 + cc];
                Us[(r0 + rr) * HSX + cc] = s;
                __syncthreads();
            }
        }

        float csr[4], rdiv[4], arr[4];
#pragma unroll
        for (int i = 0; i < 4; i++) {
            float rr2 = (float)(4 * ty + i);
            float cs = (rr2 + 1.f) * ts + 0.5f * (rr2 + 1.f) * (rr2 + 2.f);
            csr[i]  = cs;
            rdiv[i] = 1.f / (tri0 + cs);
            arr[i]  = tri0 * rdiv[i];
        }

        /* D: O = (Q @ W_avg)*a + (Q @ W_t)*(1-a)   (64 x 32) */
        float o[4][2];
        {
            float acc1[4][2] = {}, acc2[4][2] = {};
            for (int k = 0; k < 64; k++) {
                float q0[4], wa0[2], wt0[2];
#pragma unroll
                for (int i = 0; i < 4; i++) q0[i] = Qs[(4 * ty + i) * FS + k];
#pragma unroll
                for (int j = 0; j < 2; j++) {
                    wa0[j] = Wa[k * HSX + 2 * tx + j];
                    wt0[j] = Wt[k * HSX + 2 * tx + j];
                }
#pragma unroll
                for (int i = 0; i < 4; i++)
#pragma unroll
                    for (int j = 0; j < 2; j++) {
                        acc1[i][j] += q0[i] * wa0[j];
                        acc2[i][j] += q0[i] * wt0[j];
                    }
            }
#pragma unroll
            for (int i = 0; i < 4; i++)
#pragma unroll
                for (int j = 0; j < 2; j++)
                    o[i][j] = acc1[i][j] * arr[i] + acc2[i][j] * (1.f - arr[i]);
        }

        /* E: QK = Q @ K^T (full, into Ts) */
        {
            float acc[4][4] = {};
            for (int k = 0; k < 64; k++) {
                float q0[4], k0[4];
#pragma unroll
                for (int i = 0; i < 4; i++) q0[i] = Qs[(4 * ty + i) * FS + k];
#pragma unroll
                for (int j = 0; j < 4; j++) k0[j] = Ks[(4 * tx + j) * FS + k];
#pragma unroll
                for (int i = 0; i < 4; i++)
#pragma unroll
                    for (int j = 0; j < 4; j++) acc[i][j] += q0[i] * k0[j];
            }
#pragma unroll
            for (int i = 0; i < 4; i++)
#pragma unroll
                for (int j = 0; j < 4; j++)
                    Ts[(4 * ty + i) * FS + 4 * tx + j] = acc[i][j];
        }
        __syncthreads();

        /* F: O += (T_mat o QK) @ U */
        {
            for (int kp = 0; kp < 64; kp++) {
                float kf = (float)kp;
                float csk_m = kf * ts + 0.5f * kf * (kf + 1.f);
                float u0[2];
#pragma unroll
                for (int j = 0; j < 2; j++) u0[j] = Us[kp * HSX + 2 * tx + j];
#pragma unroll
                for (int i = 0; i < 4; i++) {
                    float num  = csr[i] - csk_m;
                    float sfac = (num >= 0.f) ? num * rdiv[i] : 0.f;
                    float sv   = sfac * Ts[(4 * ty + i) * FS + kp];
#pragma unroll
                    for (int j = 0; j < 2; j++) o[i][j] += sv * u0[j];
                }
            }
        }

        /* G: write raw O (RMS deferred) */
        {
            const int cidx = h * 64 + col0 + 2 * tx;
#pragma unroll
            for (int i = 0; i < 4; i++) {
                int l = chunk * 64 + 4 * ty + i;
                *(float2*)&g_o[((size_t)(b * L_DIM + l)) * D_MODEL + cidx] =
                    make_float2(o[i][0], o[i][1]);
            }
        }

        /* H: W updates (64 x 32) */
        {
            float p1[4][2] = {}, p2[4][2] = {};
            for (int r = 0; r < 64; r++) {
                float rr2  = (float)r;
                float idxr = ts + rr2 + 1.f;
                float csrr = (rr2 + 1.f) * ts + 0.5f * (rr2 + 1.f) * (rr2 + 2.f);
                float wr   = (idxr + Ssum - csrr) / denw;
                float kv[4], uv[2];
#pragma unroll
                for (int i = 0; i < 4; i++) kv[i] = Ks[r * FS + 4 * ty + i];
#pragma unroll
                for (int j = 0; j < 2; j++) uv[j] = Us[r * HSX + 2 * tx + j];
#pragma unroll
                for (int i = 0; i < 4; i++)
#pragma unroll
                    for (int j = 0; j < 2; j++) {
                        p1[i][j] += kv[i] * uv[j];
                        p2[i][j] += kv[i] * uv[j] * wr;
                    }
            }
#pragma unroll
            for (int i = 0; i < 4; i++)
#pragma unroll
                for (int j = 0; j < 2; j++) {
                    int idx2 = (4 * ty + i) * HSX + 2 * tx + j;
                    float wold = Wt[idx2], waold = Wa[idx2];
                    Wa[idx2] = coef1 * waold + coef2 * wold + p2[i][j];
                    Wt[idx2] = wold + p1[i][j];
                }
        }
    }
}

/* -------- RMS norm over head dim + fp16 hi/lo split for final GEMM ---------- */
__global__ __launch_bounds__(256) void rms_split(const float* __restrict__ rms_w)
{
    const int bl = blockIdx.x, tid = threadIdx.x;
    float4 v = ((const float4*)g_o)[(size_t)bl * 256 + tid];
    float ss = v.x * v.x + v.y * v.y + v.z * v.z + v.w * v.w;
#pragma unroll
    for (int o = 8; o > 0; o >>= 1) ss += __shfl_xor_sync(0xffffffffu, ss, o);
    float scale = rsqrtf(ss * (1.f / 64.f) + 1e-6f);
    float4 rw = ((const float4*)rms_w)[tid & 15];
    float a0 = v.x * scale * rw.x, a1 = v.y * scale * rw.y;
    float a2 = v.z * scale * rw.z, a3 = v.w * scale * rw.w;
    __half2 h01 = __floats2half2_rn(a0, a1);
    __half2 h23 = __floats2half2_rn(a2, a3);
    __half2 l01 = __floats2half2_rn(a0 - __low2float(h01), a1 - __high2float(h01));
    __half2 l23 = __floats2half2_rn(a2 - __low2float(h23), a3 - __high2float(h23));
    ((uint2*)g_oh)[(size_t)bl * 256 + tid] = make_uint2(*(uint32_t*)&h01, *(uint32_t*)&h23);
    ((uint2*)g_ol)[(size_t)bl * 256 + tid] = make_uint2(*(uint32_t*)&l01, *(uint32_t*)&l23);
}

/* ------------------------------- launcher ----------------------------------*/
extern "C" void kernel_launch(void* const* d_in, const int* in_sizes, int n_in,
                              void* d_out, int out_size)
{
    (void)in_sizes; (void)n_in; (void)out_size;
    const float* x     = (const float*)d_in[0];
    const float* Wk    = (const float*)d_in[1];
    const float* bk    = (const float*)d_in[2];
    const float* Wq    = (const float*)d_in[3];
    const float* bq    = (const float*)d_in[4];
    const float* Wv    = (const float*)d_in[5];
    const float* bv    = (const float*)d_in[6];
    const float* Wbeta = (const float*)d_in[7];
    const float* bbeta = (const float*)d_in[8];
    const float* ck    = (const float*)d_in[9];
    const float* cq    = (const float*)d_in[10];
    const float* cv    = (const float*)d_in[11];
    const float* rms_w = (const float*)d_in[12];
    const float* Wout  = (const float*)d_in[13];
    const float* bout  = (const float*)d_in[14];
    float* out = (float*)d_out;

    float *kpre, *qpre, *vpre;
    __half *xh, *xl, *oh, *ol, *wsh, *wsl;
    cudaGetSymbolAddress((void**)&kpre, g_kpre);
    cudaGetSymbolAddress((void**)&qpre, g_qpre);
    cudaGetSymbolAddress((void**)&vpre, g_vpre);
    cudaGetSymbolAddress((void**)&xh, g_xh);
    cudaGetSymbolAddress((void**)&xl, g_xl);
    cudaGetSymbolAddress((void**)&oh, g_oh);
    cudaGetSymbolAddress((void**)&ol, g_ol);
    cudaGetSymbolAddress((void**)&wsh, g_wsh);
    cudaGetSymbolAddress((void**)&wsl, g_wsl);

    split_f2h<<<(ML * D_MODEL / 4 + 255) / 256, 256>>>(
        (const float4*)x, (uint2*)xh, (uint2*)xl, ML * D_MODEL / 4);
    split_f2h<<<(DD / 4 + 255) / 256, 256>>>(
        (const float4*)Wk, (uint2*)wsh, (uint2*)wsl, DD / 4);
    split_f2h<<<(DD / 4 + 255) / 256, 256>>>(
        (const float4*)Wq, (uint2*)(wsh + DD), (uint2*)(wsl + DD), DD / 4);
    split_f2h<<<(DD / 4 + 255) / 256, 256>>>(
        (const float4*)Wv, (uint2*)(wsh + 2 * DD), (uint2*)(wsl + 2 * DD), DD / 4);
    split_f2h<<<(DD / 4 + 255) / 256, 256>>>(
        (const float4*)Wout, (uint2*)(wsh + 3 * DD), (uint2*)(wsl + 3 * DD), DD / 4);

    cudaFuncSetAttribute(gemm_qkv3, cudaFuncAttributeMaxDynamicSharedMemorySize,
                         GSM_BYTES);
    cudaFuncSetAttribute(gemm_h3b, cudaFuncAttributeMaxDynamicSharedMemorySize,
                         GSM_BYTES);

    gemm_qkv3<<<dim3(48, 64), 256, GSM_BYTES>>>(
        xh, xl, wsh, wsl, bk, bq, bv, kpre, qpre, vpre, ML, D_MODEL);

    prep_kernel<<<ML, 256>>>(x, Wbeta, bbeta, ck, cq, cv);

    size_t smem_bytes = SMEM_FLOATS * sizeof(float);
    cudaFuncSetAttribute(delta_kernel, cudaFuncAttributeMaxDynamicSharedMemorySize,
                         (int)smem_bytes);
    delta_kernel<<<2 * N_PAIR, 256, smem_bytes>>>();

    rms_split<<<ML, 256>>>(rms_w);

    gemm_h3b<<<dim3(16, 64), 256, GSM_BYTES>>>(
        oh, ol, wsh + 3 * DD, wsl + 3 * DD, bout, out, ML, D_MODEL, D_MODEL);
}